// round 5
// baseline (speedup 1.0000x reference)
#include <cuda_runtime.h>
#include <cuda_bf16.h>
#include <cstdint>

#define S_LEN   2048
#define D_MODEL 1024
#define NHEADS  16
#define HDIM    64
#define NB      2

// Scratch (allocation-free rule: static __device__ arrays)
__device__ float g_q[NB * NHEADS * S_LEN * HDIM];
__device__ float g_k[NB * NHEADS * S_LEN * HDIM];
__device__ float g_v[NB * NHEADS * S_LEN * HDIM];
__device__ float g_att[NB * S_LEN * D_MODEL];

// bf16 split copies of x and W (hi + lo)
__device__ __nv_bfloat16 g_xhi[NB * S_LEN * D_MODEL];
__device__ __nv_bfloat16 g_xlo[NB * S_LEN * D_MODEL];
__device__ __nv_bfloat16 g_whi[3 * D_MODEL * D_MODEL];
__device__ __nv_bfloat16 g_wlo[3 * D_MODEL * D_MODEL];

// ===========================================================================
// HMMA helpers (valid on base sm_100: no tcgen05, no 'a' features)
// ===========================================================================
__device__ __forceinline__ uint32_t smem_u32(const void* p) {
    uint32_t a;
    asm("{ .reg .u64 t; cvta.to.shared.u64 t, %1; cvt.u32.u64 %0, t; }"
        : "=r"(a) : "l"(p));
    return a;
}

__device__ __forceinline__ void ldsm4(uint32_t addr, uint32_t* r) {
    asm volatile("ldmatrix.sync.aligned.m8n8.x4.shared.b16 {%0,%1,%2,%3}, [%4];"
                 : "=r"(r[0]), "=r"(r[1]), "=r"(r[2]), "=r"(r[3]) : "r"(addr));
}

__device__ __forceinline__ void mma16816(float* d, const uint32_t* a,
                                         uint32_t b0, uint32_t b1) {
    asm volatile(
        "mma.sync.aligned.m16n8k16.row.col.f32.bf16.bf16.f32 "
        "{%0,%1,%2,%3}, {%4,%5,%6,%7}, {%8,%9}, {%0,%1,%2,%3};"
        : "+f"(d[0]), "+f"(d[1]), "+f"(d[2]), "+f"(d[3])
        : "r"(a[0]), "r"(a[1]), "r"(a[2]), "r"(a[3]), "r"(b0), "r"(b1));
}

#define SWZ128(off) ((off) ^ (((off) >> 3) & 0x70))

// ===========================================================================
// Kernel 0: split fp32 x / W into bf16 hi + lo pairs
// ===========================================================================
#define X_ELEMS (NB * S_LEN * D_MODEL)          // 4 M
#define W_ELEMS (3 * D_MODEL * D_MODEL)         // 3 M
#define SPLIT_QUADS ((X_ELEMS + W_ELEMS) / 4)   // 1.75 M

__global__ __launch_bounds__(256) void split_kernel(
    const float* __restrict__ x,
    const float* __restrict__ Wq,
    const float* __restrict__ Wk,
    const float* __restrict__ Wv)
{
    int gid = blockIdx.x * 256 + threadIdx.x;
    if (gid >= SPLIT_QUADS) return;
    int e4 = gid * 4;
    const float* src;
    __nv_bfloat16 *dh, *dl;
    if (e4 < X_ELEMS) {
        src = x + e4; dh = g_xhi + e4; dl = g_xlo + e4;
    } else {
        int j = e4 - X_ELEMS;
        int w = j >> 20;                  // 0..2 (1M elems per W)
        int o = j & ((1 << 20) - 1);
        src = (w == 0 ? Wq : w == 1 ? Wk : Wv) + o;
        dh = g_whi + j; dl = g_wlo + j;
    }
    float4 v = *(const float4*)src;
    __nv_bfloat16 h0 = __float2bfloat16(v.x);
    __nv_bfloat16 h1 = __float2bfloat16(v.y);
    __nv_bfloat16 h2 = __float2bfloat16(v.z);
    __nv_bfloat16 h3 = __float2bfloat16(v.w);
    __nv_bfloat16 l0 = __float2bfloat16(v.x - __bfloat162float(h0));
    __nv_bfloat16 l1 = __float2bfloat16(v.y - __bfloat162float(h1));
    __nv_bfloat16 l2 = __float2bfloat16(v.z - __bfloat162float(h2));
    __nv_bfloat16 l3 = __float2bfloat16(v.w - __bfloat162float(h3));
    *(__nv_bfloat162*)&dh[0] = __nv_bfloat162(h0, h1);
    *(__nv_bfloat162*)&dh[2] = __nv_bfloat162(h2, h3);
    *(__nv_bfloat162*)&dl[0] = __nv_bfloat162(l0, l1);
    *(__nv_bfloat162*)&dl[2] = __nv_bfloat162(l2, l3);
}

// ===========================================================================
// Kernel 1: HMMA QKV GEMM, bf16 2-split (hi*hi + hi*lo + lo*hi)
// CTA: 128 x-rows (M) x 128 features (N); K chunks of 64; 8 warps (2m x 4n),
// warp tile 64x32 = 4 m-tiles(16) x 4 n-tiles(8).
// Output written to g_q/g_k/g_v in [b, h, s, hd] layout (fp32).
// ===========================================================================
#define GK_CHUNK   64
#define GK_CHUNKS  (D_MODEL / GK_CHUNK)    // 16
#define TILE_BYTES (128 * 128)             // 128 rows x 128B (64 bf16)

#define SO_XHI     0
#define SO_XLO     (SO_XHI + TILE_BYTES)
#define SO_WHI     (SO_XLO + TILE_BYTES)
#define SO_WLO     (SO_WHI + TILE_BYTES)
#define GEMM_SMEM_BYTES (128 * 132 * 4)    // 67584 (>= 4*16384 tile bytes)

__global__ __launch_bounds__(256) void qkv_mma_kernel()
{
    extern __shared__ char sm[];
    const uint32_t smem_base = smem_u32(sm);
    const int tid  = threadIdx.x;
    const int wid  = tid >> 5;
    const int lane = tid & 31;
    const int wm   = wid & 1;             // m half (64 rows)
    const int wn   = wid >> 1;            // n quarter (32 features)

    const int fc = blockIdx.x;            // feature tile 0..7
    const int rt = blockIdx.y;            // row tile 0..31
    const int w  = blockIdx.z;            // 0..2
    const int n0 = rt * 128;              // x-row base
    const int m0 = fc * 128;              // feature base

    const __nv_bfloat16* Xh = g_xhi;
    const __nv_bfloat16* Xl = g_xlo;
    const __nv_bfloat16* Wh = g_whi + (size_t)w * D_MODEL * D_MODEL;
    const __nv_bfloat16* Wl = g_wlo + (size_t)w * D_MODEL * D_MODEL;
    float* out = (w == 0) ? g_q : (w == 1) ? g_k : g_v;

    float acc[4][4][4];
#pragma unroll
    for (int mt = 0; mt < 4; mt++)
#pragma unroll
        for (int nt = 0; nt < 4; nt++)
#pragma unroll
            for (int i = 0; i < 4; i++) acc[mt][nt][i] = 0.0f;

    // ldmatrix source addresses (fixed per thread, add tile offsets)
    const int a_row = wm * 64 + (lane & 15);
    const int a_kq  = (lane >> 4) * 8;                       // 0 or 8
    const int b_row = wn * 32 + (lane & 7) + (lane >> 4) * 8;
    const int b_kq  = ((lane >> 3) & 1) * 8;                 // 0 or 8

    for (int ch = 0; ch < GK_CHUNKS; ch++) {
        const int k0 = ch * GK_CHUNK;
        __syncthreads();   // previous chunk fully consumed
        // Load 4 tiles (xhi/xlo/whi/wlo), each 128 rows x 64 bf16, swizzled.
#pragma unroll
        for (int it = 0; it < 4; it++) {
            int e   = (it * 256 + tid) * 8;       // bf16 element index 0..8191
            int row = e >> 6;
            int col = e & 63;
            uint32_t swo = SWZ128((uint32_t)(row * 128 + col * 2));
            size_t xoff = (size_t)(n0 + row) * D_MODEL + k0 + col;
            size_t woff = (size_t)(m0 + row) * D_MODEL + k0 + col;
            *(uint4*)(sm + SO_XHI + swo) = *(const uint4*)&Xh[xoff];
            *(uint4*)(sm + SO_XLO + swo) = *(const uint4*)&Xl[xoff];
            *(uint4*)(sm + SO_WHI + swo) = *(const uint4*)&Wh[woff];
            *(uint4*)(sm + SO_WLO + swo) = *(const uint4*)&Wl[woff];
        }
        __syncthreads();

#pragma unroll
        for (int ks = 0; ks < 4; ks++) {
            const int kc = ks * 16;
            uint32_t ah[4][4], al[4][4];
#pragma unroll
            for (int mt = 0; mt < 4; mt++) {
                uint32_t off = SWZ128((uint32_t)((a_row + mt * 16) * 128 + (kc + a_kq) * 2));
                ldsm4(smem_base + SO_XHI + off, ah[mt]);
                ldsm4(smem_base + SO_XLO + off, al[mt]);
            }
            uint32_t bh[2][4], bl[2][4];
#pragma unroll
            for (int bt = 0; bt < 2; bt++) {
                uint32_t off = SWZ128((uint32_t)((b_row + bt * 16) * 128 + (kc + b_kq) * 2));
                ldsm4(smem_base + SO_WHI + off, bh[bt]);
                ldsm4(smem_base + SO_WLO + off, bl[bt]);
            }
#pragma unroll
            for (int mt = 0; mt < 4; mt++) {
#pragma unroll
                for (int nt = 0; nt < 4; nt++) {
                    int bt = nt >> 1, sb = (nt & 1) * 2;
                    mma16816(acc[mt][nt], ah[mt], bh[bt][sb], bh[bt][sb + 1]);
                    mma16816(acc[mt][nt], ah[mt], bl[bt][sb], bl[bt][sb + 1]);
                    mma16816(acc[mt][nt], al[mt], bh[bt][sb], bh[bt][sb + 1]);
                }
            }
        }
    }

    // Epilogue: stage fp32 tile in smem, then coalesced float4 stores.
    __syncthreads();
    float* dmat = (float*)sm;   // 128 x 132
    const int cr = lane >> 2;          // 0..7
    const int cc = (lane & 3) * 2;
#pragma unroll
    for (int mt = 0; mt < 4; mt++) {
#pragma unroll
        for (int nt = 0; nt < 4; nt++) {
            int r = wm * 64 + mt * 16 + cr;
            int c = wn * 32 + nt * 8 + cc;
            dmat[r * 132 + c]           = acc[mt][nt][0];
            dmat[r * 132 + c + 1]       = acc[mt][nt][1];
            dmat[(r + 8) * 132 + c]     = acc[mt][nt][2];
            dmat[(r + 8) * 132 + c + 1] = acc[mt][nt][3];
        }
    }
    __syncthreads();

    const int cq    = (tid & 15) * 4;
    const int rbase = tid >> 4;
#pragma unroll
    for (int rr = 0; rr < 8; rr++) {
        int r = rr * 16 + rbase;
        int n = n0 + r;
        int b = n >> 11;
        int s = n & (S_LEN - 1);
#pragma unroll
        for (int half = 0; half < 2; half++) {
            int head = (m0 >> 6) + half;
            float4 v = *(float4*)&dmat[r * 132 + half * 64 + cq];
            *(float4*)&out[(((size_t)(b * NHEADS + head) * S_LEN) + s) * HDIM + cq] = v;
        }
    }
}

// ---------------------------------------------------------------------------
// Kernel 2: flash attention with relative-position skew (UNCHANGED, proven)
// ---------------------------------------------------------------------------
#define SQ_OFF   0
#define SK_OFF   (65 * 65)
#define SV_OFF   (SK_OFF + 64 * 65)
#define SER_OFF  (SV_OFF + 64 * 65)
#define SP_OFF   (SER_OFF + 128 * 65)
#define SMEM_FLOATS (SP_OFF + 64 * 65)
#define SMEM_BYTES  (SMEM_FLOATS * 4)

__global__ __launch_bounds__(256) void attn_kernel(const float* __restrict__ Er)
{
    extern __shared__ float smf[];
    float* sq  = smf + SQ_OFF;
    float* sk  = smf + SK_OFF;
    float* sv  = smf + SV_OFF;
    float* ser = smf + SER_OFF;
    float* sp  = smf + SP_OFF;

    const int tid  = threadIdx.x;
    const int lane = tid & 31;
    const int wr   = tid >> 5;
    const int rl0  = wr * 8;
    const int s0   = blockIdx.x * 64;
    const int bh   = blockIdx.y;

    const float* qb = g_q + (size_t)bh * S_LEN * HDIM;
    const float* kb = g_k + (size_t)bh * S_LEN * HDIM;
    const float* vb = g_v + (size_t)bh * S_LEN * HDIM;

    for (int i4 = tid; i4 < 65 * 16; i4 += 256) {
        int r  = i4 >> 4;
        int kq = i4 & 15;
        float4 v = make_float4(0.f, 0.f, 0.f, 0.f);
        if (s0 + r < S_LEN) v = *(const float4*)&qb[(size_t)(s0 + r) * HDIM + kq * 4];
        float* dst = &sq[r * 65 + kq * 4];
        dst[0] = v.x; dst[1] = v.y; dst[2] = v.z; dst[3] = v.w;
    }

    float m_i[8], l_i[8], o_i[8][2];
#pragma unroll
    for (int r = 0; r < 8; r++) {
        m_i[r] = -1e30f; l_i[r] = 0.0f; o_i[r][0] = 0.0f; o_i[r][1] = 0.0f;
    }

    const float scale = 0.03125f;

    for (int t0 = 0; t0 < S_LEN; t0 += 64) {
        __syncthreads();

        for (int i4 = tid; i4 < 64 * 16; i4 += 256) {
            int c  = i4 >> 4;
            int kq = i4 & 15;
            float4 kv = *(const float4*)&kb[(size_t)(t0 + c) * HDIM + kq * 4];
            float* d1 = &sk[c * 65 + kq * 4];
            d1[0] = kv.x; d1[1] = kv.y; d1[2] = kv.z; d1[3] = kv.w;
            float4 vv = *(const float4*)&vb[(size_t)(t0 + c) * HDIM + kq * 4];
            float* d2 = &sv[c * 65 + kq * 4];
            d2[0] = vv.x; d2[1] = vv.y; d2[2] = vv.z; d2[3] = vv.w;
        }

        const int dlo = t0 - s0 - 63;
        for (int i4 = tid; i4 < 128 * 16; i4 += 256) {
            int di = i4 >> 4;
            int kq = i4 & 15;
            int d  = dlo + di;
            int j  = (d <= 0) ? (S_LEN - 1 + d) : (d - 2);
            float4 ev = make_float4(0.f, 0.f, 0.f, 0.f);
            if (j >= 0 && j < S_LEN) ev = *(const float4*)&Er[(size_t)j * HDIM + kq * 4];
            float* d3 = &ser[di * 65 + kq * 4];
            d3[0] = ev.x; d3[1] = ev.y; d3[2] = ev.z; d3[3] = ev.w;
        }
        __syncthreads();

        bool un[8][2];
#pragma unroll
        for (int r = 0; r < 8; r++) {
#pragma unroll
            for (int cc = 0; cc < 2; cc++) {
                int c = cc * 32 + lane;
                un[r][cc] = ((t0 + c) - (s0 + rl0 + r)) >= 2;
            }
        }

        float aqk[8][2], arl[8][2];
#pragma unroll
        for (int r = 0; r < 8; r++) {
            aqk[r][0] = 0.f; aqk[r][1] = 0.f; arl[r][0] = 0.f; arl[r][1] = 0.f;
        }

#pragma unroll 4
        for (int kk = 0; kk < HDIM; kk++) {
            float k0 = sk[lane * 65 + kk];
            float k1 = sk[(lane + 32) * 65 + kk];
            float qv[9];
#pragma unroll
            for (int r = 0; r < 9; r++) qv[r] = sq[(rl0 + r) * 65 + kk];
#pragma unroll
            for (int r = 0; r < 8; r++) {
                int diA = lane + 63 - (rl0 + r);
                float e0 = ser[diA * 65 + kk];
                float e1 = ser[(diA + 32) * 65 + kk];
                aqk[r][0] += qv[r] * k0;
                aqk[r][1] += qv[r] * k1;
                arl[r][0] += (un[r][0] ? qv[r + 1] : qv[r]) * e0;
                arl[r][1] += (un[r][1] ? qv[r + 1] : qv[r]) * e1;
            }
        }

#pragma unroll
        for (int r = 0; r < 8; r++) {
            float sc0 = (aqk[r][0] + arl[r][0]) * scale;
            float sc1 = (aqk[r][1] + arl[r][1]) * scale;
            float mx = fmaxf(sc0, sc1);
#pragma unroll
            for (int off = 16; off; off >>= 1)
                mx = fmaxf(mx, __shfl_xor_sync(0xffffffffu, mx, off));
            float mnew = fmaxf(m_i[r], mx);
            float p0 = __expf(sc0 - mnew);
            float p1 = __expf(sc1 - mnew);
            float ps = p0 + p1;
#pragma unroll
            for (int off = 16; off; off >>= 1)
                ps += __shfl_xor_sync(0xffffffffu, ps, off);
            float f = __expf(m_i[r] - mnew);
            l_i[r]  = l_i[r] * f + ps;
            m_i[r]  = mnew;
            o_i[r][0] *= f;
            o_i[r][1] *= f;
            sp[(rl0 + r) * 65 + lane]      = p0;
            sp[(rl0 + r) * 65 + lane + 32] = p1;
        }
        __syncwarp();

#pragma unroll 4
        for (int t = 0; t < 64; t++) {
            float v0 = sv[t * 65 + lane];
            float v1 = sv[t * 65 + lane + 32];
#pragma unroll
            for (int r = 0; r < 8; r++) {
                float pv = sp[(rl0 + r) * 65 + t];
                o_i[r][0] += pv * v0;
                o_i[r][1] += pv * v1;
            }
        }
    }

    const int b = bh >> 4;
    const int h = bh & 15;
#pragma unroll
    for (int r = 0; r < 8; r++) {
        int s = s0 + rl0 + r;
        float inv = 1.0f / l_i[r];
        float* op = &g_att[((size_t)(b * S_LEN + s)) * D_MODEL + h * HDIM];
        op[lane]      = o_i[r][0] * inv;
        op[lane + 32] = o_i[r][1] * inv;
    }
}

// ---------------------------------------------------------------------------
// Kernel 3: LayerNorm (unchanged)
// ---------------------------------------------------------------------------
__global__ __launch_bounds__(256) void ln_kernel(
    const float* __restrict__ lw, const float* __restrict__ lb,
    float* __restrict__ out)
{
    __shared__ float red[16];
    const int row = blockIdx.x;
    const int tid = threadIdx.x;
    const float* xr = g_att + (size_t)row * D_MODEL;

    float4 v = *(const float4*)&xr[tid * 4];
    float sum = v.x + v.y + v.z + v.w;
    float ss  = fmaf(v.x, v.x, fmaf(v.y, v.y, fmaf(v.z, v.z, v.w * v.w)));
#pragma unroll
    for (int off = 16; off; off >>= 1) {
        sum += __shfl_xor_sync(0xffffffffu, sum, off);
        ss  += __shfl_xor_sync(0xffffffffu, ss, off);
    }
    if ((tid & 31) == 0) {
        red[tid >> 5]       = sum;
        red[8 + (tid >> 5)] = ss;
    }
    __syncthreads();
    float ts = 0.f, tq = 0.f;
#pragma unroll
    for (int wv = 0; wv < 8; wv++) { ts += red[wv]; tq += red[8 + wv]; }
    float mu  = ts * (1.0f / D_MODEL);
    float var = tq * (1.0f / D_MODEL) - mu * mu;
    float rs  = rsqrtf(var + 1e-5f);

    float4 w4 = *(const float4*)&lw[tid * 4];
    float4 b4 = *(const float4*)&lb[tid * 4];
    float4 o;
    o.x = (v.x - mu) * rs * w4.x + b4.x;
    o.y = (v.y - mu) * rs * w4.y + b4.y;
    o.z = (v.z - mu) * rs * w4.z + b4.z;
    o.w = (v.w - mu) * rs * w4.w + b4.w;
    *(float4*)&out[(size_t)row * D_MODEL + tid * 4] = o;
}

// ---------------------------------------------------------------------------
extern "C" void kernel_launch(void* const* d_in, const int* in_sizes, int n_in,
                              void* d_out, int out_size)
{
    (void)in_sizes; (void)n_in; (void)out_size;
    const float* x  = (const float*)d_in[0];
    const float* Wq = (const float*)d_in[1];
    const float* Wk = (const float*)d_in[2];
    const float* Wv = (const float*)d_in[3];
    const float* Er = (const float*)d_in[4];
    const float* lw = (const float*)d_in[5];
    const float* lb = (const float*)d_in[6];
    float* out = (float*)d_out;

    split_kernel<<<(SPLIT_QUADS + 255) / 256, 256>>>(x, Wq, Wk, Wv);

    cudaFuncSetAttribute(qkv_mma_kernel,
                         cudaFuncAttributeMaxDynamicSharedMemorySize, GEMM_SMEM_BYTES);
    qkv_mma_kernel<<<dim3(D_MODEL / 128, NB * S_LEN / 128, 3), 256, GEMM_SMEM_BYTES>>>();

    cudaFuncSetAttribute(attn_kernel,
                         cudaFuncAttributeMaxDynamicSharedMemorySize, SMEM_BYTES);
    attn_kernel<<<dim3(S_LEN / 64, NB * NHEADS), 256, SMEM_BYTES>>>(Er);

    ln_kernel<<<NB * S_LEN, 256>>>(lw, lb, out);
}

// round 7
// speedup vs baseline: 2.3126x; 2.3126x over previous
#include <cuda_runtime.h>
#include <cuda_bf16.h>
#include <cstdint>

#define S_LEN 2048
#define D_MODEL 1024
#define NHEADS 16
#define HDIM 64
#define NB 2
#define BHT (NB*NHEADS)

__device__ float g_att[NB*S_LEN*D_MODEL];
__device__ __nv_bfloat16 g_xhi[NB*S_LEN*D_MODEL];
__device__ __nv_bfloat16 g_xlo[NB*S_LEN*D_MODEL];
__device__ __nv_bfloat16 g_whi[3*D_MODEL*D_MODEL];
__device__ __nv_bfloat16 g_wlo[3*D_MODEL*D_MODEL];
__device__ __nv_bfloat16 g_qh[BHT*S_LEN*HDIM];
__device__ __nv_bfloat16 g_ql[BHT*S_LEN*HDIM];
__device__ __nv_bfloat16 g_kh[BHT*S_LEN*HDIM];
__device__ __nv_bfloat16 g_kl[BHT*S_LEN*HDIM];
__device__ __nv_bfloat16 g_vth[BHT*HDIM*S_LEN];
__device__ __nv_bfloat16 g_vtl[BHT*HDIM*S_LEN];
__device__ __nv_bfloat16 g_erh[S_LEN*HDIM];
__device__ __nv_bfloat16 g_erl[S_LEN*HDIM];

__device__ __forceinline__ uint32_t smem_u32(const void* p){
    uint32_t a;
    asm("{ .reg .u64 t; cvta.to.shared.u64 t, %1; cvt.u32.u64 %0, t; }":"=r"(a):"l"(p));
    return a;
}
__device__ __forceinline__ void ldsm4(uint32_t a, uint32_t* r){
    asm volatile("ldmatrix.sync.aligned.m8n8.x4.shared.b16 {%0,%1,%2,%3}, [%4];"
        :"=r"(r[0]),"=r"(r[1]),"=r"(r[2]),"=r"(r[3]):"r"(a));
}
__device__ __forceinline__ void mma16816(float* d, const uint32_t* a, uint32_t b0, uint32_t b1){
    asm volatile("mma.sync.aligned.m16n8k16.row.col.f32.bf16.bf16.f32 "
        "{%0,%1,%2,%3}, {%4,%5,%6,%7}, {%8,%9}, {%0,%1,%2,%3};"
        :"+f"(d[0]),"+f"(d[1]),"+f"(d[2]),"+f"(d[3])
        :"r"(a[0]),"r"(a[1]),"r"(a[2]),"r"(a[3]),"r"(b0),"r"(b1));
}
__device__ __forceinline__ void pack_hilo(float x, float y, uint32_t& hi, uint32_t& lo){
    __nv_bfloat16 hx=__float2bfloat16(x), hy=__float2bfloat16(y);
    __nv_bfloat16 lx=__float2bfloat16(x-__bfloat162float(hx));
    __nv_bfloat16 ly=__float2bfloat16(y-__bfloat162float(hy));
    __nv_bfloat162 h2(hx,hy), l2(lx,ly);
    hi=*(uint32_t*)&h2; lo=*(uint32_t*)&l2;
}
#define SWZ128(o) ((o)^(((o)>>3)&0x70))

// ------------------- split -------------------
#define X_ELEMS (NB*S_LEN*D_MODEL)
#define W_ELEMS (3*D_MODEL*D_MODEL)
#define ER_ELEMS (S_LEN*HDIM)
#define SPLIT_QUADS ((X_ELEMS+W_ELEMS+ER_ELEMS)/4)

__global__ __launch_bounds__(256) void split_kernel(
    const float* __restrict__ x, const float* __restrict__ Wq,
    const float* __restrict__ Wk, const float* __restrict__ Wv,
    const float* __restrict__ Er)
{
    int gid = blockIdx.x*256 + threadIdx.x;
    if (gid >= SPLIT_QUADS) return;
    int e4 = gid*4;
    const float* src; __nv_bfloat16 *dh, *dl;
    if (e4 < X_ELEMS){ src=x+e4; dh=g_xhi+e4; dl=g_xlo+e4; }
    else if (e4 < X_ELEMS+W_ELEMS){
        int j=e4-X_ELEMS; int w=j>>20; int o=j&((1<<20)-1);
        src=(w==0?Wq:w==1?Wk:Wv)+o; dh=g_whi+j; dl=g_wlo+j;
    } else { int j=e4-X_ELEMS-W_ELEMS; src=Er+j; dh=g_erh+j; dl=g_erl+j; }
    float4 v=*(const float4*)src;
    uint32_t h01,l01,h23,l23;
    pack_hilo(v.x,v.y,h01,l01); pack_hilo(v.z,v.w,h23,l23);
    *(uint2*)dh=make_uint2(h01,h23); *(uint2*)dl=make_uint2(l01,l23);
}

// ------------------- QKV GEMM (proven core) -------------------
#define TILE_BYTES (128*128)
#define SO_XHI 0
#define SO_XLO (SO_XHI+TILE_BYTES)
#define SO_WHI (SO_XLO+TILE_BYTES)
#define SO_WLO (SO_WHI+TILE_BYTES)
#define GEMM_SMEM (128*132*4)

__global__ __launch_bounds__(256) void qkv_mma_kernel()
{
    extern __shared__ char sm[];
    const uint32_t sb = smem_u32(sm);
    const int tid=threadIdx.x, wid=tid>>5, lane=tid&31;
    const int wm=wid&1, wn=wid>>1;
    const int m0=blockIdx.x*128, n0=blockIdx.y*128, w=blockIdx.z;

    const __nv_bfloat16* Wh=g_whi+(size_t)w*D_MODEL*D_MODEL;
    const __nv_bfloat16* Wl=g_wlo+(size_t)w*D_MODEL*D_MODEL;

    float acc[4][4][4];
#pragma unroll
    for(int mt=0;mt<4;mt++)
#pragma unroll
        for(int nt=0;nt<4;nt++)
#pragma unroll
            for(int i=0;i<4;i++) acc[mt][nt][i]=0.f;

    const int a_row=wm*64+(lane&15), a_kq=(lane>>4)*8;
    const int b_row=wn*32+(lane&7)+(lane>>4)*8, b_kq=((lane>>3)&1)*8;

    for(int ch=0;ch<16;ch++){
        const int k0=ch*64;
        __syncthreads();
#pragma unroll
        for(int it=0;it<4;it++){
            int e=(it*256+tid)*8, row=e>>6, col=e&63;
            uint32_t swo=SWZ128((uint32_t)(row*128+col*2));
            size_t xo=(size_t)(n0+row)*D_MODEL+k0+col;
            size_t wo=(size_t)(m0+row)*D_MODEL+k0+col;
            *(uint4*)(sm+SO_XHI+swo)=*(const uint4*)&g_xhi[xo];
            *(uint4*)(sm+SO_XLO+swo)=*(const uint4*)&g_xlo[xo];
            *(uint4*)(sm+SO_WHI+swo)=*(const uint4*)&Wh[wo];
            *(uint4*)(sm+SO_WLO+swo)=*(const uint4*)&Wl[wo];
        }
        __syncthreads();
#pragma unroll
        for(int ks=0;ks<4;ks++){
            const int kc=ks*16;
            uint32_t ah[4][4], al[4][4];
#pragma unroll
            for(int mt=0;mt<4;mt++){
                uint32_t off=SWZ128((uint32_t)((a_row+mt*16)*128+(kc+a_kq)*2));
                ldsm4(sb+SO_XHI+off,ah[mt]); ldsm4(sb+SO_XLO+off,al[mt]);
            }
            uint32_t bh_[2][4], bl_[2][4];
#pragma unroll
            for(int bt=0;bt<2;bt++){
                uint32_t off=SWZ128((uint32_t)((b_row+bt*16)*128+(kc+b_kq)*2));
                ldsm4(sb+SO_WHI+off,bh_[bt]); ldsm4(sb+SO_WLO+off,bl_[bt]);
            }
#pragma unroll
            for(int mt=0;mt<4;mt++)
#pragma unroll
                for(int nt=0;nt<4;nt++){
                    int bt=nt>>1, s2=(nt&1)*2;
                    mma16816(acc[mt][nt],ah[mt],bh_[bt][s2],bh_[bt][s2+1]);
                    mma16816(acc[mt][nt],ah[mt],bl_[bt][s2],bl_[bt][s2+1]);
                    mma16816(acc[mt][nt],al[mt],bh_[bt][s2],bh_[bt][s2+1]);
                }
        }
    }

    __syncthreads();
    float* dmat=(float*)sm;
    const int cr=lane>>2, cc=(lane&3)*2;
#pragma unroll
    for(int mt=0;mt<4;mt++)
#pragma unroll
        for(int nt=0;nt<4;nt++){
            int r=wm*64+mt*16+cr, c=wn*32+nt*8+cc;
            dmat[r*132+c]=acc[mt][nt][0];   dmat[r*132+c+1]=acc[mt][nt][1];
            dmat[(r+8)*132+c]=acc[mt][nt][2]; dmat[(r+8)*132+c+1]=acc[mt][nt][3];
        }
    __syncthreads();

    if (w<2){
        __nv_bfloat16* oh=(w==0)?g_qh:g_kh;
        __nv_bfloat16* ol=(w==0)?g_ql:g_kl;
        const int cq=(tid&15)*4, rb=tid>>4;
#pragma unroll
        for(int rr=0;rr<8;rr++){
            int r=rr*16+rb, n=n0+r, b=n>>11, s=n&(S_LEN-1);
#pragma unroll
            for(int hf=0;hf<2;hf++){
                int head=(m0>>6)+hf;
                float4 v=*(float4*)&dmat[r*132+hf*64+cq];
                uint32_t h01,l01,h23,l23;
                pack_hilo(v.x,v.y,h01,l01); pack_hilo(v.z,v.w,h23,l23);
                size_t idx=(((size_t)(b*NHEADS+head)*S_LEN)+s)*HDIM+cq;
                *(uint2*)&oh[idx]=make_uint2(h01,h23);
                *(uint2*)&ol[idx]=make_uint2(l01,l23);
            }
        }
    } else {
        const int f=tid>>1, sh=tid&1;
        const int head=(m0>>6)+(f>>6), hd=f&63;
        const int b=n0>>11, sbase=(n0&(S_LEN-1))+sh*64;
        size_t gb=((size_t)(b*NHEADS+head)*HDIM+hd)*S_LEN+sbase;
#pragma unroll
        for(int i=0;i<64;i+=8){
            uint32_t h4[4],l4[4];
#pragma unroll
            for(int k2=0;k2<4;k2++){
                float v0=dmat[(sh*64+i+2*k2)*132+f];
                float v1=dmat[(sh*64+i+2*k2+1)*132+f];
                pack_hilo(v0,v1,h4[k2],l4[k2]);
            }
            *(uint4*)&g_vth[gb+i]=make_uint4(h4[0],h4[1],h4[2],h4[3]);
            *(uint4*)&g_vtl[gb+i]=make_uint4(l4[0],l4[1],l4[2],l4[3]);
        }
    }
}

// ------------------- attention (HMMA) -------------------
#define AQH 0
#define AQL 18432
#define AKH 36864
#define AKL 45056
#define AVH 53248
#define AVL 61440
#define AEH 69632
#define AEL 96256
#define AG  122880
#define ATT_SMEM 168960

__global__ __launch_bounds__(256) void attn_mma_kernel()
{
    extern __shared__ char sm[];
    const uint32_t sb=smem_u32(sm);
    float* gmat=(float*)(sm+AG);           // [144][80]
    const int tid=threadIdx.x, lane=tid&31, w=tid>>5;
    const int q_=lane>>2, e0=(lane&3)*2;
    const int s0=blockIdx.x*128, bh=blockIdx.y;

    const __nv_bfloat16* qh=g_qh+(size_t)bh*S_LEN*HDIM;
    const __nv_bfloat16* ql=g_ql+(size_t)bh*S_LEN*HDIM;
    const __nv_bfloat16* kh=g_kh+(size_t)bh*S_LEN*HDIM;
    const __nv_bfloat16* kl=g_kl+(size_t)bh*S_LEN*HDIM;
    const __nv_bfloat16* vth=g_vth+(size_t)bh*HDIM*S_LEN;
    const __nv_bfloat16* vtl=g_vtl+(size_t)bh*HDIM*S_LEN;

    for(int i=tid;i<144*8;i+=256){          // Q rows s0..s0+143, zero past S
        int r=i>>3, seg=i&7, s=s0+r;
        uint4 zh=make_uint4(0,0,0,0), zl=zh;
        if(s<S_LEN){ zh=*(const uint4*)&qh[(size_t)s*HDIM+seg*8];
                     zl=*(const uint4*)&ql[(size_t)s*HDIM+seg*8]; }
        uint32_t swo=SWZ128((uint32_t)(r*128+seg*16));
        *(uint4*)(sm+AQH+swo)=zh; *(uint4*)(sm+AQL+swo)=zl;
    }

    float o[8][4];
#pragma unroll
    for(int nt=0;nt<8;nt++)
#pragma unroll
        for(int i=0;i<4;i++) o[nt][i]=0.f;
    float m0_=-3.0e38f, m1_=-3.0e38f, l0_=0.f, l1_=0.f;
    const float scale=0.03125f;

    for(int t0=0;t0<S_LEN;t0+=64){
        const int delta=t0-s0;
        __syncthreads();
        for(int i=tid;i<64*8;i+=256){       // K, V^T tiles
            int r=i>>3, seg=i&7;
            uint32_t swo=SWZ128((uint32_t)(r*128+seg*16));
            *(uint4*)(sm+AKH+swo)=*(const uint4*)&kh[(size_t)(t0+r)*HDIM+seg*8];
            *(uint4*)(sm+AKL+swo)=*(const uint4*)&kl[(size_t)(t0+r)*HDIM+seg*8];
            *(uint4*)(sm+AVH+swo)=*(const uint4*)&vth[(size_t)r*S_LEN+t0+seg*8];
            *(uint4*)(sm+AVL+swo)=*(const uint4*)&vtl[(size_t)r*S_LEN+t0+seg*8];
        }
        const int u0=delta-143;             // E* window rows: u = u0 + r
        for(int i=tid;i<208*8;i+=256){
            int r=i>>3, seg=i&7, u=u0+r;
            int j=(u<=0)?(S_LEN-1+u):(u-1);
            uint4 eh=make_uint4(0,0,0,0), el=eh;
            if(j>=0 && j<S_LEN){ eh=*(const uint4*)&g_erh[(size_t)j*HDIM+seg*8];
                                 el=*(const uint4*)&g_erl[(size_t)j*HDIM+seg*8]; }
            uint32_t swo=SWZ128((uint32_t)(r*128+seg*16));
            *(uint4*)(sm+AEH+swo)=eh; *(uint4*)(sm+AEL+swo)=el;
        }
        __syncthreads();

        // prepass: G block 8 (q rows 128..143), warp w<5 covers cols 16w..16w+15
        if(w<5){
            float g8[2][4];
#pragma unroll
            for(int n2=0;n2<2;n2++)
#pragma unroll
                for(int i=0;i<4;i++) g8[n2][i]=0.f;
#pragma unroll
            for(int ks=0;ks<4;ks++){
                uint32_t a1[4],a2[4],bhf[4],blf[4];
                {
                    int row=128+(lane&15);
                    uint32_t off=SWZ128((uint32_t)(row*128+(ks*16+(lane>>4)*8)*2));
                    ldsm4(sb+AQH+off,a1); ldsm4(sb+AQL+off,a2);
                }
                {
                    int row=w*16+(lane&7)+((lane>>4)<<3);
                    uint32_t off=SWZ128((uint32_t)(row*128+(ks*16+((lane>>3)&1)*8)*2));
                    ldsm4(sb+AEH+off,bhf); ldsm4(sb+AEL+off,blf);
                }
#pragma unroll
                for(int n2=0;n2<2;n2++){
                    int s2=n2*2;
                    mma16816(g8[n2],a1,bhf[s2],bhf[s2+1]);
                    mma16816(g8[n2],a1,blf[s2],blf[s2+1]);
                    mma16816(g8[n2],a2,bhf[s2],bhf[s2+1]);
                }
            }
#pragma unroll
            for(int n2=0;n2<2;n2++){
                int col=(2*w+n2)*8+e0;
                *(float2*)&gmat[(128+q_)*80+col]=make_float2(g8[n2][0],g8[n2][1]);
                *(float2*)&gmat[(136+q_)*80+col]=make_float2(g8[n2][2],g8[n2][3]);
            }
        }

        // pass 1: QK scores, warp rows 16w..16w+15 x 64 keys
        float sacc[8][4];
#pragma unroll
        for(int nt=0;nt<8;nt++)
#pragma unroll
            for(int i=0;i<4;i++) sacc[nt][i]=0.f;
#pragma unroll
        for(int ks=0;ks<4;ks++){
            uint32_t a1[4],a2[4];
            {
                int row=16*w+(lane&15);
                uint32_t off=SWZ128((uint32_t)(row*128+(ks*16+(lane>>4)*8)*2));
                ldsm4(sb+AQH+off,a1); ldsm4(sb+AQL+off,a2);
            }
            uint32_t kb1[4][4],kb2[4][4];
#pragma unroll
            for(int bt=0;bt<4;bt++){
                int row=bt*16+(lane&7)+((lane>>4)<<3);
                uint32_t off=SWZ128((uint32_t)(row*128+(ks*16+((lane>>3)&1)*8)*2));
                ldsm4(sb+AKH+off,kb1[bt]); ldsm4(sb+AKL+off,kb2[bt]);
            }
#pragma unroll
            for(int nt=0;nt<8;nt++){
                int bt=nt>>1, s2=(nt&1)*2;
                mma16816(sacc[nt],a1,kb1[bt][s2],kb1[bt][s2+1]);
                mma16816(sacc[nt],a1,kb2[bt][s2],kb2[bt][s2+1]);
                mma16816(sacc[nt],a2,kb1[bt][s2],kb1[bt][s2+1]);
            }
        }

        // pass 2: G block w (rows 16w..16w+15 x 80 diagonals)
        {
            float gacc[10][4];
#pragma unroll
            for(int nt=0;nt<10;nt++)
#pragma unroll
                for(int i=0;i<4;i++) gacc[nt][i]=0.f;
            const int erow0=128-16*w;
#pragma unroll
            for(int ks=0;ks<4;ks++){
                uint32_t a1[4],a2[4];
                {
                    int row=16*w+(lane&15);
                    uint32_t off=SWZ128((uint32_t)(row*128+(ks*16+(lane>>4)*8)*2));
                    ldsm4(sb+AQH+off,a1); ldsm4(sb+AQL+off,a2);
                }
                uint32_t eb1[5][4],eb2[5][4];
#pragma unroll
                for(int bt=0;bt<5;bt++){
                    int row=erow0+bt*16+(lane&7)+((lane>>4)<<3);
                    uint32_t off=SWZ128((uint32_t)(row*128+(ks*16+((lane>>3)&1)*8)*2));
                    ldsm4(sb+AEH+off,eb1[bt]); ldsm4(sb+AEL+off,eb2[bt]);
                }
#pragma unroll
                for(int nt=0;nt<10;nt++){
                    int bt=nt>>1, s2=(nt&1)*2;
                    mma16816(gacc[nt],a1,eb1[bt][s2],eb1[bt][s2+1]);
                    mma16816(gacc[nt],a1,eb2[bt][s2],eb2[bt][s2+1]);
                    mma16816(gacc[nt],a2,eb1[bt][s2],eb1[bt][s2+1]);
                }
            }
#pragma unroll
            for(int nt=0;nt<10;nt++){
                int col=nt*8+e0;
                *(float2*)&gmat[(w*16+q_)*80+col]  =make_float2(gacc[nt][0],gacc[nt][1]);
                *(float2*)&gmat[(w*16+q_+8)*80+col]=make_float2(gacc[nt][2],gacc[nt][3]);
            }
        }
        __syncthreads();

        // gather rel + online softmax
        float p[8][4];
        float mx0=-3.0e38f, mx1=-3.0e38f;
        const int rho0=16*w+q_, rho1=rho0+8;
#pragma unroll
        for(int nt=0;nt<8;nt++){
#pragma unroll
            for(int e=0;e<2;e++){
                int c=nt*8+e0+e;
                {
                    int d=delta+c-rho0, rr=rho0+(d>=2), r15=rr&15;
                    float val=gmat[rr*80+c-r15+15];
                    float sc=(sacc[nt][e]+((d==1)?0.f:val))*scale;
                    p[nt][e]=sc; mx0=fmaxf(mx0,sc);
                }
                {
                    int d=delta+c-rho1, rr=rho1+(d>=2), r15=rr&15;
                    float val=gmat[rr*80+c-r15+15];
                    float sc=(sacc[nt][2+e]+((d==1)?0.f:val))*scale;
                    p[nt][2+e]=sc; mx1=fmaxf(mx1,sc);
                }
            }
        }
        mx0=fmaxf(mx0,__shfl_xor_sync(~0u,mx0,1));
        mx0=fmaxf(mx0,__shfl_xor_sync(~0u,mx0,2));
        mx1=fmaxf(mx1,__shfl_xor_sync(~0u,mx1,1));
        mx1=fmaxf(mx1,__shfl_xor_sync(~0u,mx1,2));
        float mn0=fmaxf(m0_,mx0), mn1=fmaxf(m1_,mx1);
        float f0=__expf(m0_-mn0), f1=__expf(m1_-mn1);
        float ps0=0.f, ps1=0.f;
#pragma unroll
        for(int nt=0;nt<8;nt++)
#pragma unroll
            for(int e=0;e<2;e++){
                p[nt][e]=__expf(p[nt][e]-mn0);     ps0+=p[nt][e];
                p[nt][2+e]=__expf(p[nt][2+e]-mn1); ps1+=p[nt][2+e];
            }
        ps0+=__shfl_xor_sync(~0u,ps0,1); ps0+=__shfl_xor_sync(~0u,ps0,2);
        ps1+=__shfl_xor_sync(~0u,ps1,1); ps1+=__shfl_xor_sync(~0u,ps1,2);
        l0_=l0_*f0+ps0; m0_=mn0;
        l1_=l1_*f1+ps1; m1_=mn1;
#pragma unroll
        for(int nt=0;nt<8;nt++){
            o[nt][0]*=f0; o[nt][1]*=f0; o[nt][2]*=f1; o[nt][3]*=f1;
        }

        // pack P (C-frag -> A-frag) hi/lo
        uint32_t pah[4][4], pal[4][4];
#pragma unroll
        for(int ks=0;ks<4;ks++){
            pack_hilo(p[2*ks][0],  p[2*ks][1],  pah[ks][0],pal[ks][0]);
            pack_hilo(p[2*ks][2],  p[2*ks][3],  pah[ks][1],pal[ks][1]);
            pack_hilo(p[2*ks+1][0],p[2*ks+1][1],pah[ks][2],pal[ks][2]);
            pack_hilo(p[2*ks+1][2],p[2*ks+1][3],pah[ks][3],pal[ks][3]);
        }

        // PV
#pragma unroll
        for(int ks=0;ks<4;ks++){
            uint32_t vb1[4][4],vb2[4][4];
#pragma unroll
            for(int bt=0;bt<4;bt++){
                int row=bt*16+(lane&7)+((lane>>4)<<3);
                uint32_t off=SWZ128((uint32_t)(row*128+(ks*16+((lane>>3)&1)*8)*2));
                ldsm4(sb+AVH+off,vb1[bt]); ldsm4(sb+AVL+off,vb2[bt]);
            }
#pragma unroll
            for(int nt=0;nt<8;nt++){
                int bt=nt>>1, s2=(nt&1)*2;
                mma16816(o[nt],pah[ks],vb1[bt][s2],vb1[bt][s2+1]);
                mma16816(o[nt],pah[ks],vb2[bt][s2],vb2[bt][s2+1]);
                mma16816(o[nt],pal[ks],vb1[bt][s2],vb1[bt][s2+1]);
            }
        }
    }

    const int b=bh>>4, h=bh&15;
    const float i0=1.f/l0_, i1=1.f/l1_;
    const int sr0=s0+16*w+q_, sr1=sr0+8;
#pragma unroll
    for(int nt=0;nt<8;nt++){
        int col=h*HDIM+nt*8+e0;
        *(float2*)&g_att[((size_t)(b*S_LEN+sr0))*D_MODEL+col]=make_float2(o[nt][0]*i0,o[nt][1]*i0);
        *(float2*)&g_att[((size_t)(b*S_LEN+sr1))*D_MODEL+col]=make_float2(o[nt][2]*i1,o[nt][3]*i1);
    }
}

// ------------------- LayerNorm -------------------
__global__ __launch_bounds__(256) void ln_kernel(
    const float* __restrict__ lw, const float* __restrict__ lb, float* __restrict__ out)
{
    __shared__ float red[16];
    const int row=blockIdx.x, tid=threadIdx.x;
    const float* xr=g_att+(size_t)row*D_MODEL;
    float4 v=*(const float4*)&xr[tid*4];
    float sum=v.x+v.y+v.z+v.w;
    float ss=fmaf(v.x,v.x,fmaf(v.y,v.y,fmaf(v.z,v.z,v.w*v.w)));
#pragma unroll
    for(int off=16;off;off>>=1){
        sum+=__shfl_xor_sync(~0u,sum,off);
        ss +=__shfl_xor_sync(~0u,ss,off);
    }
    if((tid&31)==0){ red[tid>>5]=sum; red[8+(tid>>5)]=ss; }
    __syncthreads();
    float ts=0.f,tq=0.f;
#pragma unroll
    for(int k=0;k<8;k++){ ts+=red[k]; tq+=red[8+k]; }
    float mu=ts*(1.f/D_MODEL), var=tq*(1.f/D_MODEL)-mu*mu;
    float rs=rsqrtf(var+1e-5f);
    float4 w4=*(const float4*)&lw[tid*4];
    float4 b4=*(const float4*)&lb[tid*4];
    float4 oo;
    oo.x=(v.x-mu)*rs*w4.x+b4.x; oo.y=(v.y-mu)*rs*w4.y+b4.y;
    oo.z=(v.z-mu)*rs*w4.z+b4.z; oo.w=(v.w-mu)*rs*w4.w+b4.w;
    *(float4*)&out[(size_t)row*D_MODEL+tid*4]=oo;
}

extern "C" void kernel_launch(void* const* d_in, const int* in_sizes, int n_in,
                              void* d_out, int out_size)
{
    (void)in_sizes; (void)n_in; (void)out_size;
    const float* x =(const float*)d_in[0];
    const float* Wq=(const float*)d_in[1];
    const float* Wk=(const float*)d_in[2];
    const float* Wv=(const float*)d_in[3];
    const float* Er=(const float*)d_in[4];
    const float* lw=(const float*)d_in[5];
    const float* lb=(const float*)d_in[6];
    float* out=(float*)d_out;

    split_kernel<<<(SPLIT_QUADS+255)/256,256>>>(x,Wq,Wk,Wv,Er);
    cudaFuncSetAttribute(qkv_mma_kernel, cudaFuncAttributeMaxDynamicSharedMemorySize, GEMM_SMEM);
    qkv_mma_kernel<<<dim3(8,32,3),256,GEMM_SMEM>>>();
    cudaFuncSetAttribute(attn_mma_kernel, cudaFuncAttributeMaxDynamicSharedMemorySize, ATT_SMEM);
    attn_mma_kernel<<<dim3(S_LEN/128,BHT),256,ATT_SMEM>>>();
    ln_kernel<<<NB*S_LEN,256>>>(lw,lb,out);
}

// round 8
// speedup vs baseline: 3.0307x; 1.3105x over previous
#include <cuda_runtime.h>
#include <cuda_bf16.h>
#include <cstdint>

#define S_LEN 2048
#define D_MODEL 1024
#define NHEADS 16
#define HDIM 64
#define NB 2
#define BHT (NB*NHEADS)

__device__ float g_att[NB*S_LEN*D_MODEL];
__device__ __nv_bfloat16 g_xhi[NB*S_LEN*D_MODEL];
__device__ __nv_bfloat16 g_xlo[NB*S_LEN*D_MODEL];
__device__ __nv_bfloat16 g_whi[3*D_MODEL*D_MODEL];
__device__ __nv_bfloat16 g_wlo[3*D_MODEL*D_MODEL];
__device__ __nv_bfloat16 g_qh[BHT*S_LEN*HDIM];
__device__ __nv_bfloat16 g_ql[BHT*S_LEN*HDIM];
__device__ __nv_bfloat16 g_kh[BHT*S_LEN*HDIM];
__device__ __nv_bfloat16 g_kl[BHT*S_LEN*HDIM];
__device__ __nv_bfloat16 g_vth[BHT*HDIM*S_LEN];
__device__ __nv_bfloat16 g_vtl[BHT*HDIM*S_LEN];
__device__ __nv_bfloat16 g_erh[S_LEN*HDIM];
__device__ __nv_bfloat16 g_erl[S_LEN*HDIM];

__device__ __forceinline__ uint32_t smem_u32(const void* p){
    uint32_t a;
    asm("{ .reg .u64 t; cvta.to.shared.u64 t, %1; cvt.u32.u64 %0, t; }":"=r"(a):"l"(p));
    return a;
}
__device__ __forceinline__ void ldsm4(uint32_t a, uint32_t* r){
    asm volatile("ldmatrix.sync.aligned.m8n8.x4.shared.b16 {%0,%1,%2,%3}, [%4];"
        :"=r"(r[0]),"=r"(r[1]),"=r"(r[2]),"=r"(r[3]):"r"(a));
}
__device__ __forceinline__ void mma16816(float* d, const uint32_t* a, uint32_t b0, uint32_t b1){
    asm volatile("mma.sync.aligned.m16n8k16.row.col.f32.bf16.bf16.f32 "
        "{%0,%1,%2,%3}, {%4,%5,%6,%7}, {%8,%9}, {%0,%1,%2,%3};"
        :"+f"(d[0]),"+f"(d[1]),"+f"(d[2]),"+f"(d[3])
        :"r"(a[0]),"r"(a[1]),"r"(a[2]),"r"(a[3]),"r"(b0),"r"(b1));
}
__device__ __forceinline__ void pack_hilo(float x, float y, uint32_t& hi, uint32_t& lo){
    __nv_bfloat16 hx=__float2bfloat16(x), hy=__float2bfloat16(y);
    __nv_bfloat16 lx=__float2bfloat16(x-__bfloat162float(hx));
    __nv_bfloat16 ly=__float2bfloat16(y-__bfloat162float(hy));
    __nv_bfloat162 h2(hx,hy), l2(lx,ly);
    hi=*(uint32_t*)&h2; lo=*(uint32_t*)&l2;
}
__device__ __forceinline__ void cpa16(uint32_t d, const void* s, bool ok){
    int sz = ok?16:0;
    asm volatile("cp.async.cg.shared.global [%0],[%1],16,%2;"::"r"(d),"l"(s),"r"(sz));
}
#define CP_COMMIT() asm volatile("cp.async.commit_group;":::"memory")
#define CP_WAIT0()  asm volatile("cp.async.wait_group 0;":::"memory")
#define SWZ128(o) ((o)^(((o)>>3)&0x70))

// ------------------- split -------------------
#define X_ELEMS (NB*S_LEN*D_MODEL)
#define W_ELEMS (3*D_MODEL*D_MODEL)
#define ER_ELEMS (S_LEN*HDIM)
#define SPLIT_QUADS ((X_ELEMS+W_ELEMS+ER_ELEMS)/4)

__global__ __launch_bounds__(256) void split_kernel(
    const float* __restrict__ x, const float* __restrict__ Wq,
    const float* __restrict__ Wk, const float* __restrict__ Wv,
    const float* __restrict__ Er)
{
    int gid = blockIdx.x*256 + threadIdx.x;
    if (gid >= SPLIT_QUADS) return;
    int e4 = gid*4;
    const float* src; __nv_bfloat16 *dh, *dl;
    if (e4 < X_ELEMS){ src=x+e4; dh=g_xhi+e4; dl=g_xlo+e4; }
    else if (e4 < X_ELEMS+W_ELEMS){
        int j=e4-X_ELEMS; int w=j>>20; int o=j&((1<<20)-1);
        src=(w==0?Wq:w==1?Wk:Wv)+o; dh=g_whi+j; dl=g_wlo+j;
    } else { int j=e4-X_ELEMS-W_ELEMS; src=Er+j; dh=g_erh+j; dl=g_erl+j; }
    float4 v=*(const float4*)src;
    uint32_t h01,l01,h23,l23;
    pack_hilo(v.x,v.y,h01,l01); pack_hilo(v.z,v.w,h23,l23);
    *(uint2*)dh=make_uint2(h01,h23); *(uint2*)dl=make_uint2(l01,l23);
}

// ------------------- QKV GEMM (proven, unchanged) -------------------
#define TILE_BYTES (128*128)
#define SO_XHI 0
#define SO_XLO (SO_XHI+TILE_BYTES)
#define SO_WHI (SO_XLO+TILE_BYTES)
#define SO_WLO (SO_WHI+TILE_BYTES)
#define GEMM_SMEM (128*132*4)

__global__ __launch_bounds__(256) void qkv_mma_kernel()
{
    extern __shared__ char sm[];
    const uint32_t sb = smem_u32(sm);
    const int tid=threadIdx.x, wid=tid>>5, lane=tid&31;
    const int wm=wid&1, wn=wid>>1;
    const int m0=blockIdx.x*128, n0=blockIdx.y*128, w=blockIdx.z;

    const __nv_bfloat16* Wh=g_whi+(size_t)w*D_MODEL*D_MODEL;
    const __nv_bfloat16* Wl=g_wlo+(size_t)w*D_MODEL*D_MODEL;

    float acc[4][4][4];
#pragma unroll
    for(int mt=0;mt<4;mt++)
#pragma unroll
        for(int nt=0;nt<4;nt++)
#pragma unroll
            for(int i=0;i<4;i++) acc[mt][nt][i]=0.f;

    const int a_row=wm*64+(lane&15), a_kq=(lane>>4)*8;
    const int b_row=wn*32+(lane&7)+(lane>>4)*8, b_kq=((lane>>3)&1)*8;

    for(int ch=0;ch<16;ch++){
        const int k0=ch*64;
        __syncthreads();
#pragma unroll
        for(int it=0;it<4;it++){
            int e=(it*256+tid)*8, row=e>>6, col=e&63;
            uint32_t swo=SWZ128((uint32_t)(row*128+col*2));
            size_t xo=(size_t)(n0+row)*D_MODEL+k0+col;
            size_t wo=(size_t)(m0+row)*D_MODEL+k0+col;
            *(uint4*)(sm+SO_XHI+swo)=*(const uint4*)&g_xhi[xo];
            *(uint4*)(sm+SO_XLO+swo)=*(const uint4*)&g_xlo[xo];
            *(uint4*)(sm+SO_WHI+swo)=*(const uint4*)&Wh[wo];
            *(uint4*)(sm+SO_WLO+swo)=*(const uint4*)&Wl[wo];
        }
        __syncthreads();
#pragma unroll
        for(int ks=0;ks<4;ks++){
            const int kc=ks*16;
            uint32_t ah[4][4], al[4][4];
#pragma unroll
            for(int mt=0;mt<4;mt++){
                uint32_t off=SWZ128((uint32_t)((a_row+mt*16)*128+(kc+a_kq)*2));
                ldsm4(sb+SO_XHI+off,ah[mt]); ldsm4(sb+SO_XLO+off,al[mt]);
            }
            uint32_t bh_[2][4], bl_[2][4];
#pragma unroll
            for(int bt=0;bt<2;bt++){
                uint32_t off=SWZ128((uint32_t)((b_row+bt*16)*128+(kc+b_kq)*2));
                ldsm4(sb+SO_WHI+off,bh_[bt]); ldsm4(sb+SO_WLO+off,bl_[bt]);
            }
#pragma unroll
            for(int mt=0;mt<4;mt++)
#pragma unroll
                for(int nt=0;nt<4;nt++){
                    int bt=nt>>1, s2=(nt&1)*2;
                    mma16816(acc[mt][nt],ah[mt],bh_[bt][s2],bh_[bt][s2+1]);
                    mma16816(acc[mt][nt],ah[mt],bl_[bt][s2],bl_[bt][s2+1]);
                    mma16816(acc[mt][nt],al[mt],bh_[bt][s2],bh_[bt][s2+1]);
                }
        }
    }

    __syncthreads();
    float* dmat=(float*)sm;
    const int cr=lane>>2, cc=(lane&3)*2;
#pragma unroll
    for(int mt=0;mt<4;mt++)
#pragma unroll
        for(int nt=0;nt<4;nt++){
            int r=wm*64+mt*16+cr, c=wn*32+nt*8+cc;
            dmat[r*132+c]=acc[mt][nt][0];   dmat[r*132+c+1]=acc[mt][nt][1];
            dmat[(r+8)*132+c]=acc[mt][nt][2]; dmat[(r+8)*132+c+1]=acc[mt][nt][3];
        }
    __syncthreads();

    if (w<2){
        __nv_bfloat16* oh=(w==0)?g_qh:g_kh;
        __nv_bfloat16* ol=(w==0)?g_ql:g_kl;
        const int cq=(tid&15)*4, rb=tid>>4;
#pragma unroll
        for(int rr=0;rr<8;rr++){
            int r=rr*16+rb, n=n0+r, b=n>>11, s=n&(S_LEN-1);
#pragma unroll
            for(int hf=0;hf<2;hf++){
                int head=(m0>>6)+hf;
                float4 v=*(float4*)&dmat[r*132+hf*64+cq];
                uint32_t h01,l01,h23,l23;
                pack_hilo(v.x,v.y,h01,l01); pack_hilo(v.z,v.w,h23,l23);
                size_t idx=(((size_t)(b*NHEADS+head)*S_LEN)+s)*HDIM+cq;
                *(uint2*)&oh[idx]=make_uint2(h01,h23);
                *(uint2*)&ol[idx]=make_uint2(l01,l23);
            }
        }
    } else {
        const int f=tid>>1, sh=tid&1;
        const int head=(m0>>6)+(f>>6), hd=f&63;
        const int b=n0>>11, sbase=(n0&(S_LEN-1))+sh*64;
        size_t gb=((size_t)(b*NHEADS+head)*HDIM+hd)*S_LEN+sbase;
#pragma unroll
        for(int i=0;i<64;i+=8){
            uint32_t h4[4],l4[4];
#pragma unroll
            for(int k2=0;k2<4;k2++){
                float v0=dmat[(sh*64+i+2*k2)*132+f];
                float v1=dmat[(sh*64+i+2*k2+1)*132+f];
                pack_hilo(v0,v1,h4[k2],l4[k2]);
            }
            *(uint4*)&g_vth[gb+i]=make_uint4(h4[0],h4[1],h4[2],h4[3]);
            *(uint4*)&g_vtl[gb+i]=make_uint4(l4[0],l4[1],l4[2],l4[3]);
        }
    }
}

// ------------------- attention (HMMA + cp.async pipeline + E ring) -------------------
// smem map: Q 36864 | K 2buf x (hi8192+lo8192) | V same | E ring 272rows x128B x2 | gmat
#define AQH 0
#define AQL 18432
#define AK  36864
#define AV  69632
#define AEH 102400
#define AEL 137216
#define AG  172032
#define ATT_SMEM 218112

__global__ __launch_bounds__(256) void attn_mma_kernel()
{
    extern __shared__ char sm[];
    const uint32_t sb=smem_u32(sm);
    float* gmat=(float*)(sm+AG);           // [144][80]
    const int tid=threadIdx.x, lane=tid&31, w=tid>>5;
    const int q_=lane>>2, e0=(lane&3)*2;
    const int s0=blockIdx.x*128, bh=blockIdx.y;

    const __nv_bfloat16* qh=g_qh+(size_t)bh*S_LEN*HDIM;
    const __nv_bfloat16* ql=g_ql+(size_t)bh*S_LEN*HDIM;
    const __nv_bfloat16* kh=g_kh+(size_t)bh*S_LEN*HDIM;
    const __nv_bfloat16* kl=g_kl+(size_t)bh*S_LEN*HDIM;
    const __nv_bfloat16* vth=g_vth+(size_t)bh*HDIM*S_LEN;
    const __nv_bfloat16* vtl=g_vtl+(size_t)bh*HDIM*S_LEN;

    for(int i=tid;i<144*8;i+=256){          // Q rows s0..s0+143, zero past S
        int r=i>>3, seg=i&7, s=s0+r;
        uint4 zh=make_uint4(0,0,0,0), zl=zh;
        if(s<S_LEN){ zh=*(const uint4*)&qh[(size_t)s*HDIM+seg*8];
                     zl=*(const uint4*)&ql[(size_t)s*HDIM+seg*8]; }
        uint32_t swo=SWZ128((uint32_t)(r*128+seg*16));
        *(uint4*)(sm+AQH+swo)=zh; *(uint4*)(sm+AQL+swo)=zl;
    }

    // prefetch tile 0: full E window (13 blocks) + K/V buf0
    for(int i=tid;i<208*8;i+=256){
        int r=i>>3, seg=i&7;
        int u=-s0-143+r;
        int j=(u<=0)?(S_LEN-1+u):(u-1);
        bool ok=(j>=0 && j<S_LEN); if(!ok) j=0;
        uint32_t swo=SWZ128((uint32_t)(r*128+seg*16));
        cpa16(sb+AEH+swo,&g_erh[(size_t)j*HDIM+seg*8],ok);
        cpa16(sb+AEL+swo,&g_erl[(size_t)j*HDIM+seg*8],ok);
    }
    for(int i=tid;i<64*8;i+=256){
        int r=i>>3, seg=i&7;
        uint32_t swo=SWZ128((uint32_t)(r*128+seg*16));
        cpa16(sb+AK+swo,     &kh[(size_t)r*HDIM+seg*8],true);
        cpa16(sb+AK+8192+swo,&kl[(size_t)r*HDIM+seg*8],true);
        cpa16(sb+AV+swo,     &vth[(size_t)r*S_LEN+seg*8],true);
        cpa16(sb+AV+8192+swo,&vtl[(size_t)r*S_LEN+seg*8],true);
    }
    CP_COMMIT();

    float o[8][4];
#pragma unroll
    for(int nt=0;nt<8;nt++)
#pragma unroll
        for(int i=0;i<4;i++) o[nt][i]=0.f;
    float m0_=-3.0e38f, m1_=-3.0e38f, l0_=0.f, l1_=0.f;
    const float scale=0.03125f;

    for(int ti=0;ti<32;ti++){
        const int t0=ti*64, delta=t0-s0;
        const uint32_t kbuf=AK+(ti&1)*16384, vbuf=AV+(ti&1)*16384;
        CP_WAIT0();
        __syncthreads();

        if(ti<31){                          // prefetch tile ti+1
            int tau=ti+1, tt0=tau*64;
            uint32_t kb2=AK+(tau&1)*16384, vb2=AV+(tau&1)*16384;
            for(int i=tid;i<64*8;i+=256){
                int r=i>>3, seg=i&7;
                uint32_t swo=SWZ128((uint32_t)(r*128+seg*16));
                cpa16(sb+kb2+swo,     &kh[(size_t)(tt0+r)*HDIM+seg*8],true);
                cpa16(sb+kb2+8192+swo,&kl[(size_t)(tt0+r)*HDIM+seg*8],true);
                cpa16(sb+vb2+swo,     &vth[(size_t)r*S_LEN+tt0+seg*8],true);
                cpa16(sb+vb2+8192+swo,&vtl[(size_t)r*S_LEN+tt0+seg*8],true);
            }
            for(int i=tid;i<64*8;i+=256){   // 4 new E blocks (lb 9..12 of window tau)
                int r=i>>3, seg=i&7;
                int u=tt0-s0+1+r;
                int j=(u<=0)?(S_LEN-1+u):(u-1);
                bool ok=(j>=0 && j<S_LEN); if(!ok) j=0;
                int pb=(4*tau+9+(r>>4))%17;
                uint32_t swo=SWZ128((uint32_t)((pb*16+(r&15))*128+seg*16));
                cpa16(sb+AEH+swo,&g_erh[(size_t)j*HDIM+seg*8],ok);
                cpa16(sb+AEL+swo,&g_erl[(size_t)j*HDIM+seg*8],ok);
            }
            CP_COMMIT();
        }

        // prepass: G block 8 (q rows 128..143), warps w<5
        if(w<5){
            float g8[2][4];
#pragma unroll
            for(int n2=0;n2<2;n2++)
#pragma unroll
                for(int i=0;i<4;i++) g8[n2][i]=0.f;
            const int pb=(4*ti+w)%17;
#pragma unroll
            for(int ks=0;ks<4;ks++){
                uint32_t a1[4],a2[4],bhf[4],blf[4];
                {
                    int row=128+(lane&15);
                    uint32_t off=SWZ128((uint32_t)(row*128+(ks*16+(lane>>4)*8)*2));
                    ldsm4(sb+AQH+off,a1); ldsm4(sb+AQL+off,a2);
                }
                {
                    int row=pb*16+(lane&7)+((lane>>4)<<3);
                    uint32_t off=SWZ128((uint32_t)(row*128+(ks*16+((lane>>3)&1)*8)*2));
                    ldsm4(sb+AEH+off,bhf); ldsm4(sb+AEL+off,blf);
                }
#pragma unroll
                for(int n2=0;n2<2;n2++){
                    int s2=n2*2;
                    mma16816(g8[n2],a1,bhf[s2],bhf[s2+1]);
                    mma16816(g8[n2],a1,blf[s2],blf[s2+1]);
                    mma16816(g8[n2],a2,bhf[s2],bhf[s2+1]);
                }
            }
#pragma unroll
            for(int n2=0;n2<2;n2++){
                int col=(2*w+n2)*8+e0;
                *(float2*)&gmat[(128+q_)*80+col]=make_float2(g8[n2][0],g8[n2][1]);
                *(float2*)&gmat[(136+q_)*80+col]=make_float2(g8[n2][2],g8[n2][3]);
            }
        }

        // pass 1: QK scores
        float sacc[8][4];
#pragma unroll
        for(int nt=0;nt<8;nt++)
#pragma unroll
            for(int i=0;i<4;i++) sacc[nt][i]=0.f;
#pragma unroll
        for(int ks=0;ks<4;ks++){
            uint32_t a1[4],a2[4];
            {
                int row=16*w+(lane&15);
                uint32_t off=SWZ128((uint32_t)(row*128+(ks*16+(lane>>4)*8)*2));
                ldsm4(sb+AQH+off,a1); ldsm4(sb+AQL+off,a2);
            }
            uint32_t kb1[4][4],kb2[4][4];
#pragma unroll
            for(int bt=0;bt<4;bt++){
                int row=bt*16+(lane&7)+((lane>>4)<<3);
                uint32_t off=SWZ128((uint32_t)(row*128+(ks*16+((lane>>3)&1)*8)*2));
                ldsm4(sb+kbuf+off,kb1[bt]); ldsm4(sb+kbuf+8192+off,kb2[bt]);
            }
#pragma unroll
            for(int nt=0;nt<8;nt++){
                int bt=nt>>1, s2=(nt&1)*2;
                mma16816(sacc[nt],a1,kb1[bt][s2],kb1[bt][s2+1]);
                mma16816(sacc[nt],a1,kb2[bt][s2],kb2[bt][s2+1]);
                mma16816(sacc[nt],a2,kb1[bt][s2],kb1[bt][s2+1]);
            }
        }

        // pass 2: G block w (80 diagonals)
        {
            float gacc[10][4];
#pragma unroll
            for(int nt=0;nt<10;nt++)
#pragma unroll
                for(int i=0;i<4;i++) gacc[nt][i]=0.f;
#pragma unroll
            for(int ks=0;ks<4;ks++){
                uint32_t a1[4],a2[4];
                {
                    int row=16*w+(lane&15);
                    uint32_t off=SWZ128((uint32_t)(row*128+(ks*16+(lane>>4)*8)*2));
                    ldsm4(sb+AQH+off,a1); ldsm4(sb+AQL+off,a2);
                }
                uint32_t eb1[5][4],eb2[5][4];
#pragma unroll
                for(int bt=0;bt<5;bt++){
                    int pb=(4*ti+8-w+bt)%17;
                    int row=pb*16+(lane&7)+((lane>>4)<<3);
                    uint32_t off=SWZ128((uint32_t)(row*128+(ks*16+((lane>>3)&1)*8)*2));
                    ldsm4(sb+AEH+off,eb1[bt]); ldsm4(sb+AEL+off,eb2[bt]);
                }
#pragma unroll
                for(int nt=0;nt<10;nt++){
                    int bt=nt>>1, s2=(nt&1)*2;
                    mma16816(gacc[nt],a1,eb1[bt][s2],eb1[bt][s2+1]);
                    mma16816(gacc[nt],a1,eb2[bt][s2],eb2[bt][s2+1]);
                    mma16816(gacc[nt],a2,eb1[bt][s2],eb1[bt][s2+1]);
                }
            }
#pragma unroll
            for(int nt=0;nt<10;nt++){
                int col=nt*8+e0;
                *(float2*)&gmat[(w*16+q_)*80+col]  =make_float2(gacc[nt][0],gacc[nt][1]);
                *(float2*)&gmat[(w*16+q_+8)*80+col]=make_float2(gacc[nt][2],gacc[nt][3]);
            }
        }
        __syncthreads();

        // gather rel + online softmax
        float p[8][4];
        float mx0=-3.0e38f, mx1=-3.0e38f;
        const int rho0=16*w+q_, rho1=rho0+8;
#pragma unroll
        for(int nt=0;nt<8;nt++){
#pragma unroll
            for(int e=0;e<2;e++){
                int c=nt*8+e0+e;
                {
                    int d=delta+c-rho0, rr=rho0+(d>=2), r15=rr&15;
                    float val=gmat[rr*80+c-r15+15];
                    float sc=(sacc[nt][e]+((d==1)?0.f:val))*scale;
                    p[nt][e]=sc; mx0=fmaxf(mx0,sc);
                }
                {
                    int d=delta+c-rho1, rr=rho1+(d>=2), r15=rr&15;
                    float val=gmat[rr*80+c-r15+15];
                    float sc=(sacc[nt][2+e]+((d==1)?0.f:val))*scale;
                    p[nt][2+e]=sc; mx1=fmaxf(mx1,sc);
                }
            }
        }
        mx0=fmaxf(mx0,__shfl_xor_sync(~0u,mx0,1));
        mx0=fmaxf(mx0,__shfl_xor_sync(~0u,mx0,2));
        mx1=fmaxf(mx1,__shfl_xor_sync(~0u,mx1,1));
        mx1=fmaxf(mx1,__shfl_xor_sync(~0u,mx1,2));
        float mn0=fmaxf(m0_,mx0), mn1=fmaxf(m1_,mx1);
        float f0=__expf(m0_-mn0), f1=__expf(m1_-mn1);
        float ps0=0.f, ps1=0.f;
#pragma unroll
        for(int nt=0;nt<8;nt++)
#pragma unroll
            for(int e=0;e<2;e++){
                p[nt][e]=__expf(p[nt][e]-mn0);     ps0+=p[nt][e];
                p[nt][2+e]=__expf(p[nt][2+e]-mn1); ps1+=p[nt][2+e];
            }
        ps0+=__shfl_xor_sync(~0u,ps0,1); ps0+=__shfl_xor_sync(~0u,ps0,2);
        ps1+=__shfl_xor_sync(~0u,ps1,1); ps1+=__shfl_xor_sync(~0u,ps1,2);
        l0_=l0_*f0+ps0; m0_=mn0;
        l1_=l1_*f1+ps1; m1_=mn1;
#pragma unroll
        for(int nt=0;nt<8;nt++){
            o[nt][0]*=f0; o[nt][1]*=f0; o[nt][2]*=f1; o[nt][3]*=f1;
        }

        // pack P (C-frag -> A-frag) hi/lo
        uint32_t pah[4][4], pal[4][4];
#pragma unroll
        for(int ks=0;ks<4;ks++){
            pack_hilo(p[2*ks][0],  p[2*ks][1],  pah[ks][0],pal[ks][0]);
            pack_hilo(p[2*ks][2],  p[2*ks][3],  pah[ks][1],pal[ks][1]);
            pack_hilo(p[2*ks+1][0],p[2*ks+1][1],pah[ks][2],pal[ks][2]);
            pack_hilo(p[2*ks+1][2],p[2*ks+1][3],pah[ks][3],pal[ks][3]);
        }

        // PV
#pragma unroll
        for(int ks=0;ks<4;ks++){
            uint32_t vb1[4][4],vb2[4][4];
#pragma unroll
            for(int bt=0;bt<4;bt++){
                int row=bt*16+(lane&7)+((lane>>4)<<3);
                uint32_t off=SWZ128((uint32_t)(row*128+(ks*16+((lane>>3)&1)*8)*2));
                ldsm4(sb+vbuf+off,vb1[bt]); ldsm4(sb+vbuf+8192+off,vb2[bt]);
            }
#pragma unroll
            for(int nt=0;nt<8;nt++){
                int bt=nt>>1, s2=(nt&1)*2;
                mma16816(o[nt],pah[ks],vb1[bt][s2],vb1[bt][s2+1]);
                mma16816(o[nt],pah[ks],vb2[bt][s2],vb2[bt][s2+1]);
                mma16816(o[nt],pal[ks],vb1[bt][s2],vb1[bt][s2+1]);
            }
        }
    }

    const int b=bh>>4, h=bh&15;
    const float i0=1.f/l0_, i1=1.f/l1_;
    const int sr0=s0+16*w+q_, sr1=sr0+8;
#pragma unroll
    for(int nt=0;nt<8;nt++){
        int col=h*HDIM+nt*8+e0;
        *(float2*)&g_att[((size_t)(b*S_LEN+sr0))*D_MODEL+col]=make_float2(o[nt][0]*i0,o[nt][1]*i0);
        *(float2*)&g_att[((size_t)(b*S_LEN+sr1))*D_MODEL+col]=make_float2(o[nt][2]*i1,o[nt][3]*i1);
    }
}

// ------------------- LayerNorm -------------------
__global__ __launch_bounds__(256) void ln_kernel(
    const float* __restrict__ lw, const float* __restrict__ lb, float* __restrict__ out)
{
    __shared__ float red[16];
    const int row=blockIdx.x, tid=threadIdx.x;
    const float* xr=g_att+(size_t)row*D_MODEL;
    float4 v=*(const float4*)&xr[tid*4];
    float sum=v.x+v.y+v.z+v.w;
    float ss=fmaf(v.x,v.x,fmaf(v.y,v.y,fmaf(v.z,v.z,v.w*v.w)));
#pragma unroll
    for(int off=16;off;off>>=1){
        sum+=__shfl_xor_sync(~0u,sum,off);
        ss +=__shfl_xor_sync(~0u,ss,off);
    }
    if((tid&31)==0){ red[tid>>5]=sum; red[8+(tid>>5)]=ss; }
    __syncthreads();
    float ts=0.f,tq=0.f;
#pragma unroll
    for(int k=0;k<8;k++){ ts+=red[k]; tq+=red[8+k]; }
    float mu=ts*(1.f/D_MODEL), var=tq*(1.f/D_MODEL)-mu*mu;
    float rs=rsqrtf(var+1e-5f);
    float4 w4=*(const float4*)&lw[tid*4];
    float4 b4=*(const float4*)&lb[tid*4];
    float4 oo;
    oo.x=(v.x-mu)*rs*w4.x+b4.x; oo.y=(v.y-mu)*rs*w4.y+b4.y;
    oo.z=(v.z-mu)*rs*w4.z+b4.z; oo.w=(v.w-mu)*rs*w4.w+b4.w;
    *(float4*)&out[(size_t)row*D_MODEL+tid*4]=oo;
}

extern "C" void kernel_launch(void* const* d_in, const int* in_sizes, int n_in,
                              void* d_out, int out_size)
{
    (void)in_sizes; (void)n_in; (void)out_size;
    const float* x =(const float*)d_in[0];
    const float* Wq=(const float*)d_in[1];
    const float* Wk=(const float*)d_in[2];
    const float* Wv=(const float*)d_in[3];
    const float* Er=(const float*)d_in[4];
    const float* lw=(const float*)d_in[5];
    const float* lb=(const float*)d_in[6];
    float* out=(float*)d_out;

    split_kernel<<<(SPLIT_QUADS+255)/256,256>>>(x,Wq,Wk,Wv,Er);
    cudaFuncSetAttribute(qkv_mma_kernel, cudaFuncAttributeMaxDynamicSharedMemorySize, GEMM_SMEM);
    qkv_mma_kernel<<<dim3(8,32,3),256,GEMM_SMEM>>>();
    cudaFuncSetAttribute(attn_mma_kernel, cudaFuncAttributeMaxDynamicSharedMemorySize, ATT_SMEM);
    attn_mma_kernel<<<dim3(S_LEN/128,BHT),256,ATT_SMEM>>>();
    ln_kernel<<<NB*S_LEN,256>>>(lw,lb,out);
}

// round 9
// speedup vs baseline: 6.0157x; 1.9849x over previous
#include <cuda_runtime.h>
#include <cuda_fp16.h>
#include <cstdint>

#define S_LEN 2048
#define D_MODEL 1024
#define NHEADS 16
#define HDIM 64
#define NB 2
#define BHT (NB*NHEADS)

__device__ float g_att[NB*S_LEN*D_MODEL];
__device__ __half g_xh[NB*S_LEN*D_MODEL];
__device__ __half g_wh[3*D_MODEL*D_MODEL];
__device__ __half g_qh[BHT*S_LEN*HDIM];
__device__ __half g_kh[BHT*S_LEN*HDIM];
__device__ __half g_vth[BHT*HDIM*S_LEN];
__device__ __half g_erh[S_LEN*HDIM];

__device__ __forceinline__ uint32_t smem_u32(const void* p){
    uint32_t a;
    asm("{ .reg .u64 t; cvta.to.shared.u64 t, %1; cvt.u32.u64 %0, t; }":"=r"(a):"l"(p));
    return a;
}
__device__ __forceinline__ void ldsm4(uint32_t a, uint32_t* r){
    asm volatile("ldmatrix.sync.aligned.m8n8.x4.shared.b16 {%0,%1,%2,%3}, [%4];"
        :"=r"(r[0]),"=r"(r[1]),"=r"(r[2]),"=r"(r[3]):"r"(a));
}
__device__ __forceinline__ void mmah(float* d, const uint32_t* a, uint32_t b0, uint32_t b1){
    asm volatile("mma.sync.aligned.m16n8k16.row.col.f32.f16.f16.f32 "
        "{%0,%1,%2,%3}, {%4,%5,%6,%7}, {%8,%9}, {%0,%1,%2,%3};"
        :"+f"(d[0]),"+f"(d[1]),"+f"(d[2]),"+f"(d[3])
        :"r"(a[0]),"r"(a[1]),"r"(a[2]),"r"(a[3]),"r"(b0),"r"(b1));
}
__device__ __forceinline__ uint32_t packh(float x, float y){
    __half2 h=__floats2half2_rn(x,y);
    return *(uint32_t*)&h;
}
__device__ __forceinline__ void cpa16(uint32_t d, const void* s, bool ok){
    int sz = ok?16:0;
    asm volatile("cp.async.cg.shared.global [%0],[%1],16,%2;"::"r"(d),"l"(s),"r"(sz));
}
#define CP_COMMIT() asm volatile("cp.async.commit_group;":::"memory")
#define CP_WAIT0()  asm volatile("cp.async.wait_group 0;":::"memory")
#define SWZ128(o) ((o)^(((o)>>3)&0x70))

// ------------------- convert fp32 -> fp16 -------------------
#define X_ELEMS (NB*S_LEN*D_MODEL)
#define W_ELEMS (3*D_MODEL*D_MODEL)
#define CV_QUADS ((X_ELEMS+W_ELEMS+S_LEN*HDIM)/4)

__global__ __launch_bounds__(256) void convert_kernel(
    const float* __restrict__ x, const float* __restrict__ Wq,
    const float* __restrict__ Wk, const float* __restrict__ Wv,
    const float* __restrict__ Er)
{
    int gid = blockIdx.x*256 + threadIdx.x;
    if (gid >= CV_QUADS) return;
    int e4 = gid*4;
    const float* src; __half* dst;
    if (e4 < X_ELEMS){ src=x+e4; dst=g_xh+e4; }
    else if (e4 < X_ELEMS+W_ELEMS){
        int j=e4-X_ELEMS; int w=j>>20; int o=j&((1<<20)-1);
        src=(w==0?Wq:w==1?Wk:Wv)+o; dst=g_wh+j;
    } else { int j=e4-X_ELEMS-W_ELEMS; src=Er+j; dst=g_erh+j; }
    float4 v=*(const float4*)src;
    *(uint2*)dst=make_uint2(packh(v.x,v.y),packh(v.z,v.w));
}

// ------------------- QKV GEMM: fp16 single, cp.async double-buffered -------------------
// buffer b: X tile at b, W tile at b+16384 (each 128 rows x 128B)
#define GEMM_SMEM 67584

__global__ __launch_bounds__(256) void qkv_mma_kernel()
{
    extern __shared__ char sm[];
    const uint32_t sb = smem_u32(sm);
    const int tid=threadIdx.x, wid=tid>>5, lane=tid&31;
    const int wm=wid&1, wn=wid>>1;
    const int m0=blockIdx.x*128, n0=blockIdx.y*128, w=blockIdx.z;
    const __half* Wp=g_wh+(size_t)w*D_MODEL*D_MODEL;

    float acc[4][4][4];
#pragma unroll
    for(int mt=0;mt<4;mt++)
#pragma unroll
        for(int nt=0;nt<4;nt++)
#pragma unroll
            for(int i=0;i<4;i++) acc[mt][nt][i]=0.f;

    const int a_row=wm*64+(lane&15), a_kq=(lane>>4)*8;
    const int b_row=wn*32+(lane&7)+(lane>>4)*8, b_kq=((lane>>3)&1)*8;

    // prologue: prefetch chunk 0 into buffer 0
    for(int i=tid;i<1024;i+=256){
        int r=i>>3, seg=i&7;
        uint32_t swo=SWZ128((uint32_t)(r*128+seg*16));
        cpa16(sb+swo,       &g_xh[(size_t)(n0+r)*D_MODEL+seg*8],true);
        cpa16(sb+16384+swo, &Wp[(size_t)(m0+r)*D_MODEL+seg*8],true);
    }
    CP_COMMIT();

    for(int ch=0;ch<16;ch++){
        CP_WAIT0(); __syncthreads();
        if(ch<15){
            const int k0=(ch+1)*64;
            const uint32_t bb=((ch+1)&1)*32768;
            for(int i=tid;i<1024;i+=256){
                int r=i>>3, seg=i&7;
                uint32_t swo=SWZ128((uint32_t)(r*128+seg*16));
                cpa16(sb+bb+swo,       &g_xh[(size_t)(n0+r)*D_MODEL+k0+seg*8],true);
                cpa16(sb+bb+16384+swo, &Wp[(size_t)(m0+r)*D_MODEL+k0+seg*8],true);
            }
            CP_COMMIT();
        }
        const uint32_t bb=(ch&1)*32768;
#pragma unroll
        for(int ks=0;ks<4;ks++){
            const int kc=ks*16;
            uint32_t ah[4][4];
#pragma unroll
            for(int mt=0;mt<4;mt++){
                uint32_t off=SWZ128((uint32_t)((a_row+mt*16)*128+(kc+a_kq)*2));
                ldsm4(sb+bb+off,ah[mt]);
            }
            uint32_t bf[2][4];
#pragma unroll
            for(int bt=0;bt<2;bt++){
                uint32_t off=SWZ128((uint32_t)((b_row+bt*16)*128+(kc+b_kq)*2));
                ldsm4(sb+bb+16384+off,bf[bt]);
            }
#pragma unroll
            for(int mt=0;mt<4;mt++)
#pragma unroll
                for(int nt=0;nt<4;nt++)
                    mmah(acc[mt][nt],ah[mt],bf[nt>>1][(nt&1)*2],bf[nt>>1][(nt&1)*2+1]);
        }
    }

    __syncthreads();
    float* dmat=(float*)sm;   // 128 x 132 overlays buffers
    const int cr=lane>>2, cc=(lane&3)*2;
#pragma unroll
    for(int mt=0;mt<4;mt++)
#pragma unroll
        for(int nt=0;nt<4;nt++){
            int r=wm*64+mt*16+cr, c=wn*32+nt*8+cc;
            dmat[r*132+c]=acc[mt][nt][0];   dmat[r*132+c+1]=acc[mt][nt][1];
            dmat[(r+8)*132+c]=acc[mt][nt][2]; dmat[(r+8)*132+c+1]=acc[mt][nt][3];
        }
    __syncthreads();

    if (w<2){
        __half* oh=(w==0)?g_qh:g_kh;
        const int cq=(tid&15)*4, rb=tid>>4;
#pragma unroll
        for(int rr=0;rr<8;rr++){
            int r=rr*16+rb, n=n0+r, b=n>>11, s=n&(S_LEN-1);
#pragma unroll
            for(int hf=0;hf<2;hf++){
                int head=(m0>>6)+hf;
                float4 v=*(float4*)&dmat[r*132+hf*64+cq];
                size_t idx=(((size_t)(b*NHEADS+head)*S_LEN)+s)*HDIM+cq;
                *(uint2*)&oh[idx]=make_uint2(packh(v.x,v.y),packh(v.z,v.w));
            }
        }
    } else {
        const int f=tid>>1, sh=tid&1;
        const int head=(m0>>6)+(f>>6), hd=f&63;
        const int b=n0>>11, sbase=(n0&(S_LEN-1))+sh*64;
        size_t gb=((size_t)(b*NHEADS+head)*HDIM+hd)*S_LEN+sbase;
#pragma unroll
        for(int i=0;i<64;i+=8){
            uint32_t h4[4];
#pragma unroll
            for(int k2=0;k2<4;k2++)
                h4[k2]=packh(dmat[(sh*64+i+2*k2)*132+f],dmat[(sh*64+i+2*k2+1)*132+f]);
            *(uint4*)&g_vth[gb+i]=make_uint4(h4[0],h4[1],h4[2],h4[3]);
        }
    }
}

// ------------------- attention: fp16 single + cp.async + E ring -------------------
#define AQ 0
#define AK 18432
#define AV 34816
#define AE 51200
#define AG 86016
#define ATT_SMEM 132096

__global__ __launch_bounds__(256) void attn_mma_kernel()
{
    extern __shared__ char sm[];
    const uint32_t sb=smem_u32(sm);
    float* gmat=(float*)(sm+AG);           // [144][80]
    const int tid=threadIdx.x, lane=tid&31, w=tid>>5;
    const int q_=lane>>2, e0=(lane&3)*2;
    const int s0=blockIdx.x*128, bh=blockIdx.y;

    const __half* qh=g_qh+(size_t)bh*S_LEN*HDIM;
    const __half* kh=g_kh+(size_t)bh*S_LEN*HDIM;
    const __half* vth=g_vth+(size_t)bh*HDIM*S_LEN;

    for(int i=tid;i<144*8;i+=256){          // Q rows s0..s0+143, zero past S
        int r=i>>3, seg=i&7, s=s0+r;
        uint4 z=make_uint4(0,0,0,0);
        if(s<S_LEN) z=*(const uint4*)&qh[(size_t)s*HDIM+seg*8];
        *(uint4*)(sm+AQ+SWZ128((uint32_t)(r*128+seg*16)))=z;
    }

    // prefetch tile 0: full E window (13 blocks) + K/V buf0
    for(int i=tid;i<208*8;i+=256){
        int r=i>>3, seg=i&7;
        int u=-s0-143+r;
        int j=(u<=0)?(S_LEN-1+u):(u-1);
        bool ok=(j>=0 && j<S_LEN); if(!ok) j=0;
        cpa16(sb+AE+SWZ128((uint32_t)(r*128+seg*16)),&g_erh[(size_t)j*HDIM+seg*8],ok);
    }
    for(int i=tid;i<64*8;i+=256){
        int r=i>>3, seg=i&7;
        uint32_t swo=SWZ128((uint32_t)(r*128+seg*16));
        cpa16(sb+AK+swo,&kh[(size_t)r*HDIM+seg*8],true);
        cpa16(sb+AV+swo,&vth[(size_t)r*S_LEN+seg*8],true);
    }
    CP_COMMIT();

    float o[8][4];
#pragma unroll
    for(int nt=0;nt<8;nt++)
#pragma unroll
        for(int i=0;i<4;i++) o[nt][i]=0.f;
    float m0_=-3.0e38f, m1_=-3.0e38f, l0_=0.f, l1_=0.f;
    const float scale=0.03125f;

    for(int ti=0;ti<32;ti++){
        const int t0=ti*64, delta=t0-s0;
        const uint32_t kbuf=AK+(ti&1)*8192, vbuf=AV+(ti&1)*8192;
        CP_WAIT0();
        __syncthreads();

        if(ti<31){                          // prefetch tile ti+1
            int tau=ti+1, tt0=tau*64;
            uint32_t kb2=AK+(tau&1)*8192, vb2=AV+(tau&1)*8192;
            for(int i=tid;i<64*8;i+=256){
                int r=i>>3, seg=i&7;
                uint32_t swo=SWZ128((uint32_t)(r*128+seg*16));
                cpa16(sb+kb2+swo,&kh[(size_t)(tt0+r)*HDIM+seg*8],true);
                cpa16(sb+vb2+swo,&vth[(size_t)r*S_LEN+tt0+seg*8],true);
            }
            for(int i=tid;i<64*8;i+=256){   // 4 new E ring blocks
                int r=i>>3, seg=i&7;
                int u=tt0-s0+1+r;
                int j=(u<=0)?(S_LEN-1+u):(u-1);
                bool ok=(j>=0 && j<S_LEN); if(!ok) j=0;
                int pb=(4*tau+9+(r>>4))%17;
                cpa16(sb+AE+SWZ128((uint32_t)((pb*16+(r&15))*128+seg*16)),
                      &g_erh[(size_t)j*HDIM+seg*8],ok);
            }
            CP_COMMIT();
        }

        // prepass: G block 8 (q rows 128..143), warps w<5
        if(w<5){
            float g8[2][4];
#pragma unroll
            for(int n2=0;n2<2;n2++)
#pragma unroll
                for(int i=0;i<4;i++) g8[n2][i]=0.f;
            const int pb=(4*ti+w)%17;
#pragma unroll
            for(int ks=0;ks<4;ks++){
                uint32_t a1[4],bf[4];
                {
                    int row=128+(lane&15);
                    ldsm4(sb+AQ+SWZ128((uint32_t)(row*128+(ks*16+(lane>>4)*8)*2)),a1);
                }
                {
                    int row=pb*16+(lane&7)+((lane>>4)<<3);
                    ldsm4(sb+AE+SWZ128((uint32_t)(row*128+(ks*16+((lane>>3)&1)*8)*2)),bf);
                }
#pragma unroll
                for(int n2=0;n2<2;n2++)
                    mmah(g8[n2],a1,bf[n2*2],bf[n2*2+1]);
            }
#pragma unroll
            for(int n2=0;n2<2;n2++){
                int col=(2*w+n2)*8+e0;
                *(float2*)&gmat[(128+q_)*80+col]=make_float2(g8[n2][0],g8[n2][1]);
                *(float2*)&gmat[(136+q_)*80+col]=make_float2(g8[n2][2],g8[n2][3]);
            }
        }

        // pass 1: QK scores
        float sacc[8][4];
#pragma unroll
        for(int nt=0;nt<8;nt++)
#pragma unroll
            for(int i=0;i<4;i++) sacc[nt][i]=0.f;
#pragma unroll
        for(int ks=0;ks<4;ks++){
            uint32_t a1[4];
            {
                int row=16*w+(lane&15);
                ldsm4(sb+AQ+SWZ128((uint32_t)(row*128+(ks*16+(lane>>4)*8)*2)),a1);
            }
            uint32_t kb[4][4];
#pragma unroll
            for(int bt=0;bt<4;bt++){
                int row=bt*16+(lane&7)+((lane>>4)<<3);
                ldsm4(sb+kbuf+SWZ128((uint32_t)(row*128+(ks*16+((lane>>3)&1)*8)*2)),kb[bt]);
            }
#pragma unroll
            for(int nt=0;nt<8;nt++)
                mmah(sacc[nt],a1,kb[nt>>1][(nt&1)*2],kb[nt>>1][(nt&1)*2+1]);
        }

        // pass 2: G block w (80 diagonals)
        {
            float gacc[10][4];
#pragma unroll
            for(int nt=0;nt<10;nt++)
#pragma unroll
                for(int i=0;i<4;i++) gacc[nt][i]=0.f;
#pragma unroll
            for(int ks=0;ks<4;ks++){
                uint32_t a1[4];
                {
                    int row=16*w+(lane&15);
                    ldsm4(sb+AQ+SWZ128((uint32_t)(row*128+(ks*16+(lane>>4)*8)*2)),a1);
                }
                uint32_t eb[5][4];
#pragma unroll
                for(int bt=0;bt<5;bt++){
                    int pb=(4*ti+8-w+bt)%17;
                    int row=pb*16+(lane&7)+((lane>>4)<<3);
                    ldsm4(sb+AE+SWZ128((uint32_t)(row*128+(ks*16+((lane>>3)&1)*8)*2)),eb[bt]);
                }
#pragma unroll
                for(int nt=0;nt<10;nt++)
                    mmah(gacc[nt],a1,eb[nt>>1][(nt&1)*2],eb[nt>>1][(nt&1)*2+1]);
            }
#pragma unroll
            for(int nt=0;nt<10;nt++){
                int col=nt*8+e0;
                *(float2*)&gmat[(w*16+q_)*80+col]  =make_float2(gacc[nt][0],gacc[nt][1]);
                *(float2*)&gmat[(w*16+q_+8)*80+col]=make_float2(gacc[nt][2],gacc[nt][3]);
            }
        }
        __syncthreads();

        // gather rel + online softmax
        float p[8][4];
        float mx0=-3.0e38f, mx1=-3.0e38f;
        const int rho0=16*w+q_, rho1=rho0+8;
#pragma unroll
        for(int nt=0;nt<8;nt++){
#pragma unroll
            for(int e=0;e<2;e++){
                int c=nt*8+e0+e;
                {
                    int d=delta+c-rho0, rr=rho0+(d>=2), r15=rr&15;
                    float val=gmat[rr*80+c-r15+15];
                    float sc=(sacc[nt][e]+((d==1)?0.f:val))*scale;
                    p[nt][e]=sc; mx0=fmaxf(mx0,sc);
                }
                {
                    int d=delta+c-rho1, rr=rho1+(d>=2), r15=rr&15;
                    float val=gmat[rr*80+c-r15+15];
                    float sc=(sacc[nt][2+e]+((d==1)?0.f:val))*scale;
                    p[nt][2+e]=sc; mx1=fmaxf(mx1,sc);
                }
            }
        }
        mx0=fmaxf(mx0,__shfl_xor_sync(~0u,mx0,1));
        mx0=fmaxf(mx0,__shfl_xor_sync(~0u,mx0,2));
        mx1=fmaxf(mx1,__shfl_xor_sync(~0u,mx1,1));
        mx1=fmaxf(mx1,__shfl_xor_sync(~0u,mx1,2));
        float mn0=fmaxf(m0_,mx0), mn1=fmaxf(m1_,mx1);
        float f0=__expf(m0_-mn0), f1=__expf(m1_-mn1);
        float ps0=0.f, ps1=0.f;
#pragma unroll
        for(int nt=0;nt<8;nt++)
#pragma unroll
            for(int e=0;e<2;e++){
                p[nt][e]=__expf(p[nt][e]-mn0);     ps0+=p[nt][e];
                p[nt][2+e]=__expf(p[nt][2+e]-mn1); ps1+=p[nt][2+e];
            }
        ps0+=__shfl_xor_sync(~0u,ps0,1); ps0+=__shfl_xor_sync(~0u,ps0,2);
        ps1+=__shfl_xor_sync(~0u,ps1,1); ps1+=__shfl_xor_sync(~0u,ps1,2);
        l0_=l0_*f0+ps0; m0_=mn0;
        l1_=l1_*f1+ps1; m1_=mn1;
#pragma unroll
        for(int nt=0;nt<8;nt++){
            o[nt][0]*=f0; o[nt][1]*=f0; o[nt][2]*=f1; o[nt][3]*=f1;
        }

        // pack P (C-frag -> A-frag), fp16 single
        uint32_t pa[4][4];
#pragma unroll
        for(int ks=0;ks<4;ks++){
            pa[ks][0]=packh(p[2*ks][0],  p[2*ks][1]);
            pa[ks][1]=packh(p[2*ks][2],  p[2*ks][3]);
            pa[ks][2]=packh(p[2*ks+1][0],p[2*ks+1][1]);
            pa[ks][3]=packh(p[2*ks+1][2],p[2*ks+1][3]);
        }

        // PV
#pragma unroll
        for(int ks=0;ks<4;ks++){
            uint32_t vb[4][4];
#pragma unroll
            for(int bt=0;bt<4;bt++){
                int row=bt*16+(lane&7)+((lane>>4)<<3);
                ldsm4(sb+vbuf+SWZ128((uint32_t)(row*128+(ks*16+((lane>>3)&1)*8)*2)),vb[bt]);
            }
#pragma unroll
            for(int nt=0;nt<8;nt++)
                mmah(o[nt],pa[ks],vb[nt>>1][(nt&1)*2],vb[nt>>1][(nt&1)*2+1]);
        }
    }

    const int b=bh>>4, h=bh&15;
    const float i0=1.f/l0_, i1=1.f/l1_;
    const int sr0=s0+16*w+q_, sr1=sr0+8;
#pragma unroll
    for(int nt=0;nt<8;nt++){
        int col=h*HDIM+nt*8+e0;
        *(float2*)&g_att[((size_t)(b*S_LEN+sr0))*D_MODEL+col]=make_float2(o[nt][0]*i0,o[nt][1]*i0);
        *(float2*)&g_att[((size_t)(b*S_LEN+sr1))*D_MODEL+col]=make_float2(o[nt][2]*i1,o[nt][3]*i1);
    }
}

// ------------------- LayerNorm -------------------
__global__ __launch_bounds__(256) void ln_kernel(
    const float* __restrict__ lw, const float* __restrict__ lb, float* __restrict__ out)
{
    __shared__ float red[16];
    const int row=blockIdx.x, tid=threadIdx.x;
    const float* xr=g_att+(size_t)row*D_MODEL;
    float4 v=*(const float4*)&xr[tid*4];
    float sum=v.x+v.y+v.z+v.w;
    float ss=fmaf(v.x,v.x,fmaf(v.y,v.y,fmaf(v.z,v.z,v.w*v.w)));
#pragma unroll
    for(int off=16;off;off>>=1){
        sum+=__shfl_xor_sync(~0u,sum,off);
        ss +=__shfl_xor_sync(~0u,ss,off);
    }
    if((tid&31)==0){ red[tid>>5]=sum; red[8+(tid>>5)]=ss; }
    __syncthreads();
    float ts=0.f,tq=0.f;
#pragma unroll
    for(int k=0;k<8;k++){ ts+=red[k]; tq+=red[8+k]; }
    float mu=ts*(1.f/D_MODEL), var=tq*(1.f/D_MODEL)-mu*mu;
    float rs=rsqrtf(var+1e-5f);
    float4 w4=*(const float4*)&lw[tid*4];
    float4 b4=*(const float4*)&lb[tid*4];
    float4 oo;
    oo.x=(v.x-mu)*rs*w4.x+b4.x; oo.y=(v.y-mu)*rs*w4.y+b4.y;
    oo.z=(v.z-mu)*rs*w4.z+b4.z; oo.w=(v.w-mu)*rs*w4.w+b4.w;
    *(float4*)&out[(size_t)row*D_MODEL+tid*4]=oo;
}

extern "C" void kernel_launch(void* const* d_in, const int* in_sizes, int n_in,
                              void* d_out, int out_size)
{
    (void)in_sizes; (void)n_in; (void)out_size;
    const float* x =(const float*)d_in[0];
    const float* Wq=(const float*)d_in[1];
    const float* Wk=(const float*)d_in[2];
    const float* Wv=(const float*)d_in[3];
    const float* Er=(const float*)d_in[4];
    const float* lw=(const float*)d_in[5];
    const float* lb=(const float*)d_in[6];
    float* out=(float*)d_out;

    convert_kernel<<<(CV_QUADS+255)/256,256>>>(x,Wq,Wk,Wv,Er);
    cudaFuncSetAttribute(qkv_mma_kernel, cudaFuncAttributeMaxDynamicSharedMemorySize, GEMM_SMEM);
    qkv_mma_kernel<<<dim3(8,32,3),256,GEMM_SMEM>>>();
    cudaFuncSetAttribute(attn_mma_kernel, cudaFuncAttributeMaxDynamicSharedMemorySize, ATT_SMEM);
    attn_mma_kernel<<<dim3(S_LEN/128,BHT),256,ATT_SMEM>>>();
    ln_kernel<<<NB*S_LEN,256>>>(lw,lb,out);
}

// round 10
// speedup vs baseline: 6.5946x; 1.0962x over previous
#include <cuda_runtime.h>
#include <cuda_fp16.h>
#include <cstdint>

#define S_LEN 2048
#define D_MODEL 1024
#define NHEADS 16
#define HDIM 64
#define NB 2
#define BHT (NB*NHEADS)

__device__ float g_att[NB*S_LEN*D_MODEL];
__device__ __half g_xh[NB*S_LEN*D_MODEL];
__device__ __half g_wh[3*D_MODEL*D_MODEL];
__device__ __half g_qh[BHT*S_LEN*HDIM];
__device__ __half g_kh[BHT*S_LEN*HDIM];
__device__ __half g_vth[BHT*HDIM*S_LEN];
__device__ __half g_erh[S_LEN*HDIM];

__device__ __forceinline__ uint32_t smem_u32(const void* p){
    uint32_t a;
    asm("{ .reg .u64 t; cvta.to.shared.u64 t, %1; cvt.u32.u64 %0, t; }":"=r"(a):"l"(p));
    return a;
}
__device__ __forceinline__ void ldsm4(uint32_t a, uint32_t* r){
    asm volatile("ldmatrix.sync.aligned.m8n8.x4.shared.b16 {%0,%1,%2,%3}, [%4];"
        :"=r"(r[0]),"=r"(r[1]),"=r"(r[2]),"=r"(r[3]):"r"(a));
}
__device__ __forceinline__ void mmah(float* d, const uint32_t* a, uint32_t b0, uint32_t b1){
    asm volatile("mma.sync.aligned.m16n8k16.row.col.f32.f16.f16.f32 "
        "{%0,%1,%2,%3}, {%4,%5,%6,%7}, {%8,%9}, {%0,%1,%2,%3};"
        :"+f"(d[0]),"+f"(d[1]),"+f"(d[2]),"+f"(d[3])
        :"r"(a[0]),"r"(a[1]),"r"(a[2]),"r"(a[3]),"r"(b0),"r"(b1));
}
__device__ __forceinline__ uint32_t packh(float x, float y){
    __half2 h=__floats2half2_rn(x,y);
    return *(uint32_t*)&h;
}
__device__ __forceinline__ void cpa16(uint32_t d, const void* s, bool ok){
    int sz = ok?16:0;
    asm volatile("cp.async.cg.shared.global [%0],[%1],16,%2;"::"r"(d),"l"(s),"r"(sz));
}
#define CP_COMMIT() asm volatile("cp.async.commit_group;":::"memory")
#define CP_WAIT0()  asm volatile("cp.async.wait_group 0;":::"memory")
#define SWZ128(o) ((o)^(((o)>>3)&0x70))

// ------------------- convert fp32 -> fp16 -------------------
#define X_ELEMS (NB*S_LEN*D_MODEL)
#define W_ELEMS (3*D_MODEL*D_MODEL)
#define CV_QUADS ((X_ELEMS+W_ELEMS+S_LEN*HDIM)/4)

__global__ __launch_bounds__(256) void convert_kernel(
    const float* __restrict__ x, const float* __restrict__ Wq,
    const float* __restrict__ Wk, const float* __restrict__ Wv,
    const float* __restrict__ Er)
{
    int gid = blockIdx.x*256 + threadIdx.x;
    if (gid >= CV_QUADS) return;
    int e4 = gid*4;
    const float* src; __half* dst;
    if (e4 < X_ELEMS){ src=x+e4; dst=g_xh+e4; }
    else if (e4 < X_ELEMS+W_ELEMS){
        int j=e4-X_ELEMS; int w=j>>20; int o=j&((1<<20)-1);
        src=(w==0?Wq:w==1?Wk:Wv)+o; dst=g_wh+j;
    } else { int j=e4-X_ELEMS-W_ELEMS; src=Er+j; dst=g_erh+j; }
    float4 v=*(const float4*)src;
    *(uint2*)dst=make_uint2(packh(v.x,v.y),packh(v.z,v.w));
}

// ------------------- QKV GEMM: fp16 single, cp.async double-buffered -------------------
#define GEMM_SMEM 67584

__global__ __launch_bounds__(256,2) void qkv_mma_kernel()
{
    extern __shared__ char sm[];
    const uint32_t sb = smem_u32(sm);
    const int tid=threadIdx.x, wid=tid>>5, lane=tid&31;
    const int wm=wid&1, wn=wid>>1;
    const int m0=blockIdx.x*128, n0=blockIdx.y*128, w=blockIdx.z;
    const __half* Wp=g_wh+(size_t)w*D_MODEL*D_MODEL;

    float acc[4][4][4];
#pragma unroll
    for(int mt=0;mt<4;mt++)
#pragma unroll
        for(int nt=0;nt<4;nt++)
#pragma unroll
            for(int i=0;i<4;i++) acc[mt][nt][i]=0.f;

    const int a_row=wm*64+(lane&15), a_kq=(lane>>4)*8;
    const int b_row=wn*32+(lane&7)+(lane>>4)*8, b_kq=((lane>>3)&1)*8;

    for(int i=tid;i<1024;i+=256){
        int r=i>>3, seg=i&7;
        uint32_t swo=SWZ128((uint32_t)(r*128+seg*16));
        cpa16(sb+swo,       &g_xh[(size_t)(n0+r)*D_MODEL+seg*8],true);
        cpa16(sb+16384+swo, &Wp[(size_t)(m0+r)*D_MODEL+seg*8],true);
    }
    CP_COMMIT();

    for(int ch=0;ch<16;ch++){
        CP_WAIT0(); __syncthreads();
        if(ch<15){
            const int k0=(ch+1)*64;
            const uint32_t bb=((ch+1)&1)*32768;
            for(int i=tid;i<1024;i+=256){
                int r=i>>3, seg=i&7;
                uint32_t swo=SWZ128((uint32_t)(r*128+seg*16));
                cpa16(sb+bb+swo,       &g_xh[(size_t)(n0+r)*D_MODEL+k0+seg*8],true);
                cpa16(sb+bb+16384+swo, &Wp[(size_t)(m0+r)*D_MODEL+k0+seg*8],true);
            }
            CP_COMMIT();
        }
        const uint32_t bb=(ch&1)*32768;
#pragma unroll
        for(int ks=0;ks<4;ks++){
            const int kc=ks*16;
            uint32_t ah[4][4];
#pragma unroll
            for(int mt=0;mt<4;mt++){
                uint32_t off=SWZ128((uint32_t)((a_row+mt*16)*128+(kc+a_kq)*2));
                ldsm4(sb+bb+off,ah[mt]);
            }
            uint32_t bf[2][4];
#pragma unroll
            for(int bt=0;bt<2;bt++){
                uint32_t off=SWZ128((uint32_t)((b_row+bt*16)*128+(kc+b_kq)*2));
                ldsm4(sb+bb+16384+off,bf[bt]);
            }
#pragma unroll
            for(int mt=0;mt<4;mt++)
#pragma unroll
                for(int nt=0;nt<4;nt++)
                    mmah(acc[mt][nt],ah[mt],bf[nt>>1][(nt&1)*2],bf[nt>>1][(nt&1)*2+1]);
        }
    }

    __syncthreads();
    float* dmat=(float*)sm;   // 128 x 132 overlays buffers
    const int cr=lane>>2, cc=(lane&3)*2;
#pragma unroll
    for(int mt=0;mt<4;mt++)
#pragma unroll
        for(int nt=0;nt<4;nt++){
            int r=wm*64+mt*16+cr, c=wn*32+nt*8+cc;
            dmat[r*132+c]=acc[mt][nt][0];   dmat[r*132+c+1]=acc[mt][nt][1];
            dmat[(r+8)*132+c]=acc[mt][nt][2]; dmat[(r+8)*132+c+1]=acc[mt][nt][3];
        }
    __syncthreads();

    if (w<2){
        __half* oh=(w==0)?g_qh:g_kh;
        const int cq=(tid&15)*4, rb=tid>>4;
#pragma unroll
        for(int rr=0;rr<8;rr++){
            int r=rr*16+rb, n=n0+r, b=n>>11, s=n&(S_LEN-1);
#pragma unroll
            for(int hf=0;hf<2;hf++){
                int head=(m0>>6)+hf;
                float4 v=*(float4*)&dmat[r*132+hf*64+cq];
                size_t idx=(((size_t)(b*NHEADS+head)*S_LEN)+s)*HDIM+cq;
                *(uint2*)&oh[idx]=make_uint2(packh(v.x,v.y),packh(v.z,v.w));
            }
        }
    } else {
        const int f=tid>>1, sh=tid&1;
        const int head=(m0>>6)+(f>>6), hd=f&63;
        const int b=n0>>11, sbase=(n0&(S_LEN-1))+sh*64;
        size_t gb=((size_t)(b*NHEADS+head)*HDIM+hd)*S_LEN+sbase;
#pragma unroll
        for(int i=0;i<64;i+=8){
            uint32_t h4[4];
#pragma unroll
            for(int k2=0;k2<4;k2++)
                h4[k2]=packh(dmat[(sh*64+i+2*k2)*132+f],dmat[(sh*64+i+2*k2+1)*132+f]);
            *(uint4*)&g_vth[gb+i]=make_uint4(h4[0],h4[1],h4[2],h4[3]);
        }
    }
}

// ------------------- attention: fp16 + cp.async + E ring, gmat fp16, 2 CTA/SM -------------------
#define AQ 0
#define AK 18432
#define AV 34816
#define AE 51200
#define AG 86016
#define ATT_SMEM 109056

__global__ __launch_bounds__(256,2) void attn_mma_kernel()
{
    extern __shared__ char sm[];
    const uint32_t sb=smem_u32(sm);
    __half* gmath=(__half*)(sm+AG);        // [144][80] fp16
    const int tid=threadIdx.x, lane=tid&31, w=tid>>5;
    const int q_=lane>>2, e0=(lane&3)*2;
    const int s0=blockIdx.x*128, bh=blockIdx.y;

    const __half* qh=g_qh+(size_t)bh*S_LEN*HDIM;
    const __half* kh=g_kh+(size_t)bh*S_LEN*HDIM;
    const __half* vth=g_vth+(size_t)bh*HDIM*S_LEN;

    for(int i=tid;i<144*8;i+=256){          // Q rows s0..s0+143, zero past S
        int r=i>>3, seg=i&7, s=s0+r;
        uint4 z=make_uint4(0,0,0,0);
        if(s<S_LEN) z=*(const uint4*)&qh[(size_t)s*HDIM+seg*8];
        *(uint4*)(sm+AQ+SWZ128((uint32_t)(r*128+seg*16)))=z;
    }

    for(int i=tid;i<208*8;i+=256){          // tile-0 E window
        int r=i>>3, seg=i&7;
        int u=-s0-143+r;
        int j=(u<=0)?(S_LEN-1+u):(u-1);
        bool ok=(j>=0 && j<S_LEN); if(!ok) j=0;
        cpa16(sb+AE+SWZ128((uint32_t)(r*128+seg*16)),&g_erh[(size_t)j*HDIM+seg*8],ok);
    }
    for(int i=tid;i<64*8;i+=256){
        int r=i>>3, seg=i&7;
        uint32_t swo=SWZ128((uint32_t)(r*128+seg*16));
        cpa16(sb+AK+swo,&kh[(size_t)r*HDIM+seg*8],true);
        cpa16(sb+AV+swo,&vth[(size_t)r*S_LEN+seg*8],true);
    }
    CP_COMMIT();

    float o[8][4];
#pragma unroll
    for(int nt=0;nt<8;nt++)
#pragma unroll
        for(int i=0;i<4;i++) o[nt][i]=0.f;
    float m0_=-3.0e38f, m1_=-3.0e38f, l0_=0.f, l1_=0.f;
    const float scale=0.03125f;

    for(int ti=0;ti<32;ti++){
        const int t0=ti*64, delta=t0-s0;
        const uint32_t kbuf=AK+(ti&1)*8192, vbuf=AV+(ti&1)*8192;
        CP_WAIT0();
        __syncthreads();

        if(ti<31){
            int tau=ti+1, tt0=tau*64;
            uint32_t kb2=AK+(tau&1)*8192, vb2=AV+(tau&1)*8192;
            for(int i=tid;i<64*8;i+=256){
                int r=i>>3, seg=i&7;
                uint32_t swo=SWZ128((uint32_t)(r*128+seg*16));
                cpa16(sb+kb2+swo,&kh[(size_t)(tt0+r)*HDIM+seg*8],true);
                cpa16(sb+vb2+swo,&vth[(size_t)r*S_LEN+tt0+seg*8],true);
            }
            for(int i=tid;i<64*8;i+=256){
                int r=i>>3, seg=i&7;
                int u=tt0-s0+1+r;
                int j=(u<=0)?(S_LEN-1+u):(u-1);
                bool ok=(j>=0 && j<S_LEN); if(!ok) j=0;
                int pb=(4*tau+9+(r>>4))%17;
                cpa16(sb+AE+SWZ128((uint32_t)((pb*16+(r&15))*128+seg*16)),
                      &g_erh[(size_t)j*HDIM+seg*8],ok);
            }
            CP_COMMIT();
        }

        // prepass: G block 8 (q rows 128..143), warps w<5
        if(w<5){
            float g8[2][4];
#pragma unroll
            for(int n2=0;n2<2;n2++)
#pragma unroll
                for(int i=0;i<4;i++) g8[n2][i]=0.f;
            const int pb=(4*ti+w)%17;
#pragma unroll
            for(int ks=0;ks<4;ks++){
                uint32_t a1[4],bf[4];
                {
                    int row=128+(lane&15);
                    ldsm4(sb+AQ+SWZ128((uint32_t)(row*128+(ks*16+(lane>>4)*8)*2)),a1);
                }
                {
                    int row=pb*16+(lane&7)+((lane>>4)<<3);
                    ldsm4(sb+AE+SWZ128((uint32_t)(row*128+(ks*16+((lane>>3)&1)*8)*2)),bf);
                }
#pragma unroll
                for(int n2=0;n2<2;n2++)
                    mmah(g8[n2],a1,bf[n2*2],bf[n2*2+1]);
            }
#pragma unroll
            for(int n2=0;n2<2;n2++){
                int col=(2*w+n2)*8+e0;
                *(uint32_t*)&gmath[(128+q_)*80+col]=packh(g8[n2][0],g8[n2][1]);
                *(uint32_t*)&gmath[(136+q_)*80+col]=packh(g8[n2][2],g8[n2][3]);
            }
        }

        // hoist Q A-frags for this warp's 16 rows (shared by pass 1 and pass 2)
        uint32_t a1k[4][4];
#pragma unroll
        for(int ks=0;ks<4;ks++){
            int row=16*w+(lane&15);
            ldsm4(sb+AQ+SWZ128((uint32_t)(row*128+(ks*16+(lane>>4)*8)*2)),a1k[ks]);
        }

        // pass 1: QK scores
        float sacc[8][4];
#pragma unroll
        for(int nt=0;nt<8;nt++)
#pragma unroll
            for(int i=0;i<4;i++) sacc[nt][i]=0.f;
#pragma unroll
        for(int ks=0;ks<4;ks++){
            uint32_t kb[4][4];
#pragma unroll
            for(int bt=0;bt<4;bt++){
                int row=bt*16+(lane&7)+((lane>>4)<<3);
                ldsm4(sb+kbuf+SWZ128((uint32_t)(row*128+(ks*16+((lane>>3)&1)*8)*2)),kb[bt]);
            }
#pragma unroll
            for(int nt=0;nt<8;nt++)
                mmah(sacc[nt],a1k[ks],kb[nt>>1][(nt&1)*2],kb[nt>>1][(nt&1)*2+1]);
        }

        // pass 2: G block w, streamed per-bt (low reg pressure)
#pragma unroll
        for(int bt=0;bt<5;bt++){
            float g0[4]={0.f,0.f,0.f,0.f}, g1[4]={0.f,0.f,0.f,0.f};
            const int pb=(4*ti+8-w+bt)%17;
#pragma unroll
            for(int ks=0;ks<4;ks++){
                uint32_t eb[4];
                int row=pb*16+(lane&7)+((lane>>4)<<3);
                ldsm4(sb+AE+SWZ128((uint32_t)(row*128+(ks*16+((lane>>3)&1)*8)*2)),eb);
                mmah(g0,a1k[ks],eb[0],eb[1]);
                mmah(g1,a1k[ks],eb[2],eb[3]);
            }
            int col0=(2*bt)*8+e0, col1=(2*bt+1)*8+e0;
            *(uint32_t*)&gmath[(w*16+q_)*80+col0]  =packh(g0[0],g0[1]);
            *(uint32_t*)&gmath[(w*16+q_+8)*80+col0]=packh(g0[2],g0[3]);
            *(uint32_t*)&gmath[(w*16+q_)*80+col1]  =packh(g1[0],g1[1]);
            *(uint32_t*)&gmath[(w*16+q_+8)*80+col1]=packh(g1[2],g1[3]);
        }
        __syncthreads();

        // gather rel + online softmax
        float p[8][4];
        float mx0=-3.0e38f, mx1=-3.0e38f;
        const int rho0=16*w+q_, rho1=rho0+8;
#pragma unroll
        for(int nt=0;nt<8;nt++){
#pragma unroll
            for(int e=0;e<2;e++){
                int c=nt*8+e0+e;
                {
                    int d=delta+c-rho0, rr=rho0+(d>=2), r15=rr&15;
                    float val=__half2float(gmath[rr*80+c-r15+15]);
                    float sc=(sacc[nt][e]+((d==1)?0.f:val))*scale;
                    p[nt][e]=sc; mx0=fmaxf(mx0,sc);
                }
                {
                    int d=delta+c-rho1, rr=rho1+(d>=2), r15=rr&15;
                    float val=__half2float(gmath[rr*80+c-r15+15]);
                    float sc=(sacc[nt][2+e]+((d==1)?0.f:val))*scale;
                    p[nt][2+e]=sc; mx1=fmaxf(mx1,sc);
                }
            }
        }
        mx0=fmaxf(mx0,__shfl_xor_sync(~0u,mx0,1));
        mx0=fmaxf(mx0,__shfl_xor_sync(~0u,mx0,2));
        mx1=fmaxf(mx1,__shfl_xor_sync(~0u,mx1,1));
        mx1=fmaxf(mx1,__shfl_xor_sync(~0u,mx1,2));
        float mn0=fmaxf(m0_,mx0), mn1=fmaxf(m1_,mx1);
        float f0=__expf(m0_-mn0), f1=__expf(m1_-mn1);
        float ps0=0.f, ps1=0.f;
#pragma unroll
        for(int nt=0;nt<8;nt++)
#pragma unroll
            for(int e=0;e<2;e++){
                p[nt][e]=__expf(p[nt][e]-mn0);     ps0+=p[nt][e];
                p[nt][2+e]=__expf(p[nt][2+e]-mn1); ps1+=p[nt][2+e];
            }
        ps0+=__shfl_xor_sync(~0u,ps0,1); ps0+=__shfl_xor_sync(~0u,ps0,2);
        ps1+=__shfl_xor_sync(~0u,ps1,1); ps1+=__shfl_xor_sync(~0u,ps1,2);
        l0_=l0_*f0+ps0; m0_=mn0;
        l1_=l1_*f1+ps1; m1_=mn1;
#pragma unroll
        for(int nt=0;nt<8;nt++){
            o[nt][0]*=f0; o[nt][1]*=f0; o[nt][2]*=f1; o[nt][3]*=f1;
        }

        // pack P (C-frag -> A-frag), fp16
        uint32_t pa[4][4];
#pragma unroll
        for(int ks=0;ks<4;ks++){
            pa[ks][0]=packh(p[2*ks][0],  p[2*ks][1]);
            pa[ks][1]=packh(p[2*ks][2],  p[2*ks][3]);
            pa[ks][2]=packh(p[2*ks+1][0],p[2*ks+1][1]);
            pa[ks][3]=packh(p[2*ks+1][2],p[2*ks+1][3]);
        }

        // PV
#pragma unroll
        for(int ks=0;ks<4;ks++){
            uint32_t vb[4][4];
#pragma unroll
            for(int bt=0;bt<4;bt++){
                int row=bt*16+(lane&7)+((lane>>4)<<3);
                ldsm4(sb+vbuf+SWZ128((uint32_t)(row*128+(ks*16+((lane>>3)&1)*8)*2)),vb[bt]);
            }
#pragma unroll
            for(int nt=0;nt<8;nt++)
                mmah(o[nt],pa[ks],vb[nt>>1][(nt&1)*2],vb[nt>>1][(nt&1)*2+1]);
        }
    }

    const int b=bh>>4, h=bh&15;
    const float i0=1.f/l0_, i1=1.f/l1_;
    const int sr0=s0+16*w+q_, sr1=sr0+8;
#pragma unroll
    for(int nt=0;nt<8;nt++){
        int col=h*HDIM+nt*8+e0;
        *(float2*)&g_att[((size_t)(b*S_LEN+sr0))*D_MODEL+col]=make_float2(o[nt][0]*i0,o[nt][1]*i0);
        *(float2*)&g_att[((size_t)(b*S_LEN+sr1))*D_MODEL+col]=make_float2(o[nt][2]*i1,o[nt][3]*i1);
    }
}

// ------------------- LayerNorm -------------------
__global__ __launch_bounds__(256) void ln_kernel(
    const float* __restrict__ lw, const float* __restrict__ lb, float* __restrict__ out)
{
    __shared__ float red[16];
    const int row=blockIdx.x, tid=threadIdx.x;
    const float* xr=g_att+(size_t)row*D_MODEL;
    float4 v=*(const float4*)&xr[tid*4];
    float sum=v.x+v.y+v.z+v.w;
    float ss=fmaf(v.x,v.x,fmaf(v.y,v.y,fmaf(v.z,v.z,v.w*v.w)));
#pragma unroll
    for(int off=16;off;off>>=1){
        sum+=__shfl_xor_sync(~0u,sum,off);
        ss +=__shfl_xor_sync(~0u,ss,off);
    }
    if((tid&31)==0){ red[tid>>5]=sum; red[8+(tid>>5)]=ss; }
    __syncthreads();
    float ts=0.f,tq=0.f;
#pragma unroll
    for(int k=0;k<8;k++){ ts+=red[k]; tq+=red[8+k]; }
    float mu=ts*(1.f/D_MODEL), var=tq*(1.f/D_MODEL)-mu*mu;
    float rs=rsqrtf(var+1e-5f);
    float4 w4=*(const float4*)&lw[tid*4];
    float4 b4=*(const float4*)&lb[tid*4];
    float4 oo;
    oo.x=(v.x-mu)*rs*w4.x+b4.x; oo.y=(v.y-mu)*rs*w4.y+b4.y;
    oo.z=(v.z-mu)*rs*w4.z+b4.z; oo.w=(v.w-mu)*rs*w4.w+b4.w;
    *(float4*)&out[(size_t)row*D_MODEL+tid*4]=oo;
}

extern "C" void kernel_launch(void* const* d_in, const int* in_sizes, int n_in,
                              void* d_out, int out_size)
{
    (void)in_sizes; (void)n_in; (void)out_size;
    const float* x =(const float*)d_in[0];
    const float* Wq=(const float*)d_in[1];
    const float* Wk=(const float*)d_in[2];
    const float* Wv=(const float*)d_in[3];
    const float* Er=(const float*)d_in[4];
    const float* lw=(const float*)d_in[5];
    const float* lb=(const float*)d_in[6];
    float* out=(float*)d_out;

    convert_kernel<<<(CV_QUADS+255)/256,256>>>(x,Wq,Wk,Wv,Er);
    cudaFuncSetAttribute(qkv_mma_kernel, cudaFuncAttributeMaxDynamicSharedMemorySize, GEMM_SMEM);
    qkv_mma_kernel<<<dim3(8,32,3),256,GEMM_SMEM>>>();
    cudaFuncSetAttribute(attn_mma_kernel, cudaFuncAttributeMaxDynamicSharedMemorySize, ATT_SMEM);
    attn_mma_kernel<<<dim3(S_LEN/128,BHT),256,ATT_SMEM>>>();
    ln_kernel<<<NB*S_LEN,256>>>(lw,lb,out);
}

// round 11
// speedup vs baseline: 6.7234x; 1.0195x over previous
#include <cuda_runtime.h>
#include <cuda_fp16.h>
#include <cstdint>

#define S_LEN 2048
#define D_MODEL 1024
#define NHEADS 16
#define HDIM 64
#define NB 2
#define BHT (NB*NHEADS)

__device__ float g_att[NB*S_LEN*D_MODEL];
__device__ __half g_xh[NB*S_LEN*D_MODEL];
__device__ __half g_wh[3*D_MODEL*D_MODEL];
__device__ __half g_qh[BHT*S_LEN*HDIM];
__device__ __half g_kh[BHT*S_LEN*HDIM];
__device__ __half g_vth[BHT*HDIM*S_LEN];
__device__ __half g_erh[S_LEN*HDIM];

__device__ __forceinline__ uint32_t smem_u32(const void* p){
    uint32_t a;
    asm("{ .reg .u64 t; cvta.to.shared.u64 t, %1; cvt.u32.u64 %0, t; }":"=r"(a):"l"(p));
    return a;
}
__device__ __forceinline__ void ldsm4(uint32_t a, uint32_t* r){
    asm volatile("ldmatrix.sync.aligned.m8n8.x4.shared.b16 {%0,%1,%2,%3}, [%4];"
        :"=r"(r[0]),"=r"(r[1]),"=r"(r[2]),"=r"(r[3]):"r"(a));
}
__device__ __forceinline__ void mmah(float* d, const uint32_t* a, uint32_t b0, uint32_t b1){
    asm volatile("mma.sync.aligned.m16n8k16.row.col.f32.f16.f16.f32 "
        "{%0,%1,%2,%3}, {%4,%5,%6,%7}, {%8,%9}, {%0,%1,%2,%3};"
        :"+f"(d[0]),"+f"(d[1]),"+f"(d[2]),"+f"(d[3])
        :"r"(a[0]),"r"(a[1]),"r"(a[2]),"r"(a[3]),"r"(b0),"r"(b1));
}
__device__ __forceinline__ uint32_t packh(float x, float y){
    __half2 h=__floats2half2_rn(x,y);
    return *(uint32_t*)&h;
}
__device__ __forceinline__ void cpa16(uint32_t d, const void* s, bool ok){
    int sz = ok?16:0;
    asm volatile("cp.async.cg.shared.global [%0],[%1],16,%2;"::"r"(d),"l"(s),"r"(sz));
}
#define CP_COMMIT() asm volatile("cp.async.commit_group;":::"memory")
#define CP_WAIT0()  asm volatile("cp.async.wait_group 0;":::"memory")
#define SWZ128(o) ((o)^(((o)>>3)&0x70))

// ------------------- convert fp32 -> fp16 -------------------
#define X_ELEMS (NB*S_LEN*D_MODEL)
#define W_ELEMS (3*D_MODEL*D_MODEL)
#define CV_QUADS ((X_ELEMS+W_ELEMS+S_LEN*HDIM)/4)

__global__ __launch_bounds__(256) void convert_kernel(
    const float* __restrict__ x, const float* __restrict__ Wq,
    const float* __restrict__ Wk, const float* __restrict__ Wv,
    const float* __restrict__ Er)
{
    int gid = blockIdx.x*256 + threadIdx.x;
    if (gid >= CV_QUADS) return;
    int e4 = gid*4;
    const float* src; __half* dst;
    if (e4 < X_ELEMS){ src=x+e4; dst=g_xh+e4; }
    else if (e4 < X_ELEMS+W_ELEMS){
        int j=e4-X_ELEMS; int w=j>>20; int o=j&((1<<20)-1);
        src=(w==0?Wq:w==1?Wk:Wv)+o; dst=g_wh+j;
    } else { int j=e4-X_ELEMS-W_ELEMS; src=Er+j; dst=g_erh+j; }
    float4 v=*(const float4*)src;
    *(uint2*)dst=make_uint2(packh(v.x,v.y),packh(v.z,v.w));
}

// ------------------- QKV GEMM: fp16, cp.async double-buffered -------------------
#define GEMM_SMEM 67584

__global__ __launch_bounds__(256,2) void qkv_mma_kernel()
{
    extern __shared__ char sm[];
    const uint32_t sb = smem_u32(sm);
    const int tid=threadIdx.x, wid=tid>>5, lane=tid&31;
    const int wm=wid&1, wn=wid>>1;
    const int m0=blockIdx.x*128, n0=blockIdx.y*128, w=blockIdx.z;
    const __half* Wp=g_wh+(size_t)w*D_MODEL*D_MODEL;

    float acc[4][4][4];
#pragma unroll
    for(int mt=0;mt<4;mt++)
#pragma unroll
        for(int nt=0;nt<4;nt++)
#pragma unroll
            for(int i=0;i<4;i++) acc[mt][nt][i]=0.f;

    const int a_row=wm*64+(lane&15), a_kq=(lane>>4)*8;
    const int b_row=wn*32+(lane&7)+(lane>>4)*8, b_kq=((lane>>3)&1)*8;

    for(int i=tid;i<1024;i+=256){
        int r=i>>3, seg=i&7;
        uint32_t swo=SWZ128((uint32_t)(r*128+seg*16));
        cpa16(sb+swo,       &g_xh[(size_t)(n0+r)*D_MODEL+seg*8],true);
        cpa16(sb+16384+swo, &Wp[(size_t)(m0+r)*D_MODEL+seg*8],true);
    }
    CP_COMMIT();

    for(int ch=0;ch<16;ch++){
        CP_WAIT0(); __syncthreads();
        if(ch<15){
            const int k0=(ch+1)*64;
            const uint32_t bb=((ch+1)&1)*32768;
            for(int i=tid;i<1024;i+=256){
                int r=i>>3, seg=i&7;
                uint32_t swo=SWZ128((uint32_t)(r*128+seg*16));
                cpa16(sb+bb+swo,       &g_xh[(size_t)(n0+r)*D_MODEL+k0+seg*8],true);
                cpa16(sb+bb+16384+swo, &Wp[(size_t)(m0+r)*D_MODEL+k0+seg*8],true);
            }
            CP_COMMIT();
        }
        const uint32_t bb=(ch&1)*32768;
#pragma unroll
        for(int ks=0;ks<4;ks++){
            const int kc=ks*16;
            uint32_t ah[4][4];
#pragma unroll
            for(int mt=0;mt<4;mt++){
                uint32_t off=SWZ128((uint32_t)((a_row+mt*16)*128+(kc+a_kq)*2));
                ldsm4(sb+bb+off,ah[mt]);
            }
            uint32_t bf[2][4];
#pragma unroll
            for(int bt=0;bt<2;bt++){
                uint32_t off=SWZ128((uint32_t)((b_row+bt*16)*128+(kc+b_kq)*2));
                ldsm4(sb+bb+16384+off,bf[bt]);
            }
#pragma unroll
            for(int mt=0;mt<4;mt++)
#pragma unroll
                for(int nt=0;nt<4;nt++)
                    mmah(acc[mt][nt],ah[mt],bf[nt>>1][(nt&1)*2],bf[nt>>1][(nt&1)*2+1]);
        }
    }

    __syncthreads();
    float* dmat=(float*)sm;   // 128 x 132 overlays buffers
    const int cr=lane>>2, cc=(lane&3)*2;
#pragma unroll
    for(int mt=0;mt<4;mt++)
#pragma unroll
        for(int nt=0;nt<4;nt++){
            int r=wm*64+mt*16+cr, c=wn*32+nt*8+cc;
            dmat[r*132+c]=acc[mt][nt][0];   dmat[r*132+c+1]=acc[mt][nt][1];
            dmat[(r+8)*132+c]=acc[mt][nt][2]; dmat[(r+8)*132+c+1]=acc[mt][nt][3];
        }
    __syncthreads();

    if (w<2){
        __half* oh=(w==0)?g_qh:g_kh;
        const float qsc=(w==0)?0.03125f:1.0f;   // fold softmax scale into Q (exact pow2)
        const int cq=(tid&15)*4, rb=tid>>4;
#pragma unroll
        for(int rr=0;rr<8;rr++){
            int r=rr*16+rb, n=n0+r, b=n>>11, s=n&(S_LEN-1);
#pragma unroll
            for(int hf=0;hf<2;hf++){
                int head=(m0>>6)+hf;
                float4 v=*(float4*)&dmat[r*132+hf*64+cq];
                size_t idx=(((size_t)(b*NHEADS+head)*S_LEN)+s)*HDIM+cq;
                *(uint2*)&oh[idx]=make_uint2(packh(v.x*qsc,v.y*qsc),packh(v.z*qsc,v.w*qsc));
            }
        }
    } else {
        const int f=tid>>1, sh=tid&1;
        const int head=(m0>>6)+(f>>6), hd=f&63;
        const int b=n0>>11, sbase=(n0&(S_LEN-1))+sh*64;
        size_t gb=((size_t)(b*NHEADS+head)*HDIM+hd)*S_LEN+sbase;
#pragma unroll
        for(int i=0;i<64;i+=8){
            uint32_t h4[4];
#pragma unroll
            for(int k2=0;k2<4;k2++)
                h4[k2]=packh(dmat[(sh*64+i+2*k2)*132+f],dmat[(sh*64+i+2*k2+1)*132+f]);
            *(uint4*)&g_vth[gb+i]=make_uint4(h4[0],h4[1],h4[2],h4[3]);
        }
    }
}

// ------------------- attention: fp16 + cp.async + E row-ring + G col-ring -------------------
#define AQ 0
#define AK 18432
#define AV 34816
#define AE 51200
#define AG 86016
#define ATT_SMEM 109056

__global__ __launch_bounds__(256,2) void attn_mma_kernel()
{
    extern __shared__ char sm[];
    const uint32_t sb=smem_u32(sm);
    __half* gmath=(__half*)(sm+AG);        // [144][80] fp16, column ring (64-new/80 per tile)
    const int tid=threadIdx.x, lane=tid&31, w=tid>>5;
    const int q_=lane>>2, e0=(lane&3)*2;
    const int s0=blockIdx.x*128, bh=blockIdx.y;

    const __half* qh=g_qh+(size_t)bh*S_LEN*HDIM;
    const __half* kh=g_kh+(size_t)bh*S_LEN*HDIM;
    const __half* vth=g_vth+(size_t)bh*HDIM*S_LEN;

    for(int i=tid;i<144*8;i+=256){          // Q rows s0..s0+143, zero past S
        int r=i>>3, seg=i&7, s=s0+r;
        uint4 z=make_uint4(0,0,0,0);
        if(s<S_LEN) z=*(const uint4*)&qh[(size_t)s*HDIM+seg*8];
        *(uint4*)(sm+AQ+SWZ128((uint32_t)(r*128+seg*16)))=z;
    }

    for(int i=tid;i<208*8;i+=256){          // tile-0 E window
        int r=i>>3, seg=i&7;
        int u=-s0-143+r;
        int j=(u<=0)?(S_LEN-1+u):(u-1);
        bool ok=(j>=0 && j<S_LEN); if(!ok) j=0;
        cpa16(sb+AE+SWZ128((uint32_t)(r*128+seg*16)),&g_erh[(size_t)j*HDIM+seg*8],ok);
    }
    for(int i=tid;i<64*8;i+=256){
        int r=i>>3, seg=i&7;
        uint32_t swo=SWZ128((uint32_t)(r*128+seg*16));
        cpa16(sb+AK+swo,&kh[(size_t)r*HDIM+seg*8],true);
        cpa16(sb+AV+swo,&vth[(size_t)r*S_LEN+seg*8],true);
    }
    CP_COMMIT();

    float o[8][4];
#pragma unroll
    for(int nt=0;nt<8;nt++)
#pragma unroll
        for(int i=0;i<4;i++) o[nt][i]=0.f;
    float m0_=-3.0e38f, m1_=-3.0e38f, l0_=0.f, l1_=0.f;

    for(int ti=0;ti<32;ti++){
        const int t0=ti*64, delta=t0-s0;
        const uint32_t kbuf=AK+(ti&1)*8192, vbuf=AV+(ti&1)*8192;
        const int cb10=(8*ti)%10;            // G col-ring base (n-tile units)
        const int cb80=(64*ti)%80;           // G col-ring base (element units)
        CP_WAIT0();
        __syncthreads();

        if(ti<31){
            int tau=ti+1, tt0=tau*64;
            uint32_t kb2=AK+(tau&1)*8192, vb2=AV+(tau&1)*8192;
            for(int i=tid;i<64*8;i+=256){
                int r=i>>3, seg=i&7;
                uint32_t swo=SWZ128((uint32_t)(r*128+seg*16));
                cpa16(sb+kb2+swo,&kh[(size_t)(tt0+r)*HDIM+seg*8],true);
                cpa16(sb+vb2+swo,&vth[(size_t)r*S_LEN+tt0+seg*8],true);
            }
            for(int i=tid;i<64*8;i+=256){
                int r=i>>3, seg=i&7;
                int u=tt0-s0+1+r;
                int j=(u<=0)?(S_LEN-1+u):(u-1);
                bool ok=(j>=0 && j<S_LEN); if(!ok) j=0;
                int pb=(4*tau+9+(r>>4))%17;
                cpa16(sb+AE+SWZ128((uint32_t)((pb*16+(r&15))*128+seg*16)),
                      &g_erh[(size_t)j*HDIM+seg*8],ok);
            }
            CP_COMMIT();
        }

        // prepass: G block 8 (q rows 128..143); ti=0: 5 blocks (w<5), else 4 new (w<4, bt=w+1)
        {
            const int npre=(ti==0)?5:4;
            if(w<npre){
                const int bt=(ti==0)?w:(w+1);
                float g8[2][4];
#pragma unroll
                for(int n2=0;n2<2;n2++)
#pragma unroll
                    for(int i=0;i<4;i++) g8[n2][i]=0.f;
                const int pb=(4*ti+bt)%17;
#pragma unroll
                for(int ks=0;ks<4;ks++){
                    uint32_t a1[4],bf[4];
                    {
                        int row=128+(lane&15);
                        ldsm4(sb+AQ+SWZ128((uint32_t)(row*128+(ks*16+(lane>>4)*8)*2)),a1);
                    }
                    {
                        int row=pb*16+(lane&7)+((lane>>4)<<3);
                        ldsm4(sb+AE+SWZ128((uint32_t)(row*128+(ks*16+((lane>>3)&1)*8)*2)),bf);
                    }
                    mmah(g8[0],a1,bf[0],bf[1]);
                    mmah(g8[1],a1,bf[2],bf[3]);
                }
#pragma unroll
                for(int n2=0;n2<2;n2++){
                    int pct=cb10+2*bt+n2; if(pct>=10) pct-=10;
                    int col=pct*8+e0;
                    *(uint32_t*)&gmath[(128+q_)*80+col]=packh(g8[n2][0],g8[n2][1]);
                    *(uint32_t*)&gmath[(136+q_)*80+col]=packh(g8[n2][2],g8[n2][3]);
                }
            }
        }

        // hoist Q A-frags for this warp's 16 rows
        uint32_t a1k[4][4];
#pragma unroll
        for(int ks=0;ks<4;ks++){
            int row=16*w+(lane&15);
            ldsm4(sb+AQ+SWZ128((uint32_t)(row*128+(ks*16+(lane>>4)*8)*2)),a1k[ks]);
        }

        // pass 1: QK scores
        float sacc[8][4];
#pragma unroll
        for(int nt=0;nt<8;nt++)
#pragma unroll
            for(int i=0;i<4;i++) sacc[nt][i]=0.f;
#pragma unroll
        for(int ks=0;ks<4;ks++){
            uint32_t kb[4][4];
#pragma unroll
            for(int bt=0;bt<4;bt++){
                int row=bt*16+(lane&7)+((lane>>4)<<3);
                ldsm4(sb+kbuf+SWZ128((uint32_t)(row*128+(ks*16+((lane>>3)&1)*8)*2)),kb[bt]);
            }
#pragma unroll
            for(int nt=0;nt<8;nt++)
                mmah(sacc[nt],a1k[ks],kb[nt>>1][(nt&1)*2],kb[nt>>1][(nt&1)*2+1]);
        }

        // pass 2: G block w, only NEW window blocks (bt>=1 for ti>0)
        const int btLo=(ti==0)?0:1;
        for(int bt=btLo;bt<5;bt++){
            float g0[4]={0.f,0.f,0.f,0.f}, g1[4]={0.f,0.f,0.f,0.f};
            const int pb=(4*ti+8-w+bt)%17;
#pragma unroll
            for(int ks=0;ks<4;ks++){
                uint32_t eb[4];
                int row=pb*16+(lane&7)+((lane>>4)<<3);
                ldsm4(sb+AE+SWZ128((uint32_t)(row*128+(ks*16+((lane>>3)&1)*8)*2)),eb);
                mmah(g0,a1k[ks],eb[0],eb[1]);
                mmah(g1,a1k[ks],eb[2],eb[3]);
            }
            int pct0=cb10+2*bt;   if(pct0>=10) pct0-=10;
            int pct1=cb10+2*bt+1; if(pct1>=10) pct1-=10;
            int col0=pct0*8+e0, col1=pct1*8+e0;
            *(uint32_t*)&gmath[(w*16+q_)*80+col0]  =packh(g0[0],g0[1]);
            *(uint32_t*)&gmath[(w*16+q_+8)*80+col0]=packh(g0[2],g0[3]);
            *(uint32_t*)&gmath[(w*16+q_)*80+col1]  =packh(g1[0],g1[1]);
            *(uint32_t*)&gmath[(w*16+q_+8)*80+col1]=packh(g1[2],g1[3]);
        }
        __syncthreads();

        // gather rel + online softmax (base/threshold form; q pre-scaled so no *scale)
        const int rho0=16*w+q_, rho1=rho0+8;
        int cThr0=rho0-delta+2, cThr1=rho1-delta+2;
        int KA0=15-(rho0&15)+cb80;     if(KA0>=80) KA0-=80;
        int KB0=15-((rho0+1)&15)+cb80; if(KB0>=80) KB0-=80;
        int KA1=15-(rho1&15)+cb80;     if(KA1>=80) KA1-=80;
        int KB1=15-((rho1+1)&15)+cb80; if(KB1>=80) KB1-=80;
        const int bA0=rho0*80+KA0, wA0=80-KA0;
        const int bB0=(rho0+1)*80+KB0, wB0=80-KB0;
        const int bA1=rho1*80+KA1, wA1=80-KA1;
        const int bB1=(rho1+1)*80+KB1, wB1=80-KB1;

        float p[8][4];
        float mx0=-3.0e38f, mx1=-3.0e38f;
#pragma unroll
        for(int nt=0;nt<8;nt++){
#pragma unroll
            for(int e=0;e<2;e++){
                int c=nt*8+e0+e;
                {
                    int idx=(c>=cThr0)?(bB0+c-((c>=wB0)?80:0)):(bA0+c-((c>=wA0)?80:0));
                    float val=__half2float(gmath[idx]);
                    float sc=sacc[nt][e]+((c==cThr0-1)?0.f:val);
                    p[nt][e]=sc; mx0=fmaxf(mx0,sc);
                }
                {
                    int idx=(c>=cThr1)?(bB1+c-((c>=wB1)?80:0)):(bA1+c-((c>=wA1)?80:0));
                    float val=__half2float(gmath[idx]);
                    float sc=sacc[nt][2+e]+((c==cThr1-1)?0.f:val);
                    p[nt][2+e]=sc; mx1=fmaxf(mx1,sc);
                }
            }
        }
        mx0=fmaxf(mx0,__shfl_xor_sync(~0u,mx0,1));
        mx0=fmaxf(mx0,__shfl_xor_sync(~0u,mx0,2));
        mx1=fmaxf(mx1,__shfl_xor_sync(~0u,mx1,1));
        mx1=fmaxf(mx1,__shfl_xor_sync(~0u,mx1,2));
        float mn0=fmaxf(m0_,mx0), mn1=fmaxf(m1_,mx1);
        float f0=__expf(m0_-mn0), f1=__expf(m1_-mn1);
        float ps0=0.f, ps1=0.f;
#pragma unroll
        for(int nt=0;nt<8;nt++)
#pragma unroll
            for(int e=0;e<2;e++){
                p[nt][e]=__expf(p[nt][e]-mn0);     ps0+=p[nt][e];
                p[nt][2+e]=__expf(p[nt][2+e]-mn1); ps1+=p[nt][2+e];
            }
        ps0+=__shfl_xor_sync(~0u,ps0,1); ps0+=__shfl_xor_sync(~0u,ps0,2);
        ps1+=__shfl_xor_sync(~0u,ps1,1); ps1+=__shfl_xor_sync(~0u,ps1,2);
        l0_=l0_*f0+ps0; m0_=mn0;
        l1_=l1_*f1+ps1; m1_=mn1;
#pragma unroll
        for(int nt=0;nt<8;nt++){
            o[nt][0]*=f0; o[nt][1]*=f0; o[nt][2]*=f1; o[nt][3]*=f1;
        }

        // pack P (C-frag -> A-frag), fp16
        uint32_t pa[4][4];
#pragma unroll
        for(int ks=0;ks<4;ks++){
            pa[ks][0]=packh(p[2*ks][0],  p[2*ks][1]);
            pa[ks][1]=packh(p[2*ks][2],  p[2*ks][3]);
            pa[ks][2]=packh(p[2*ks+1][0],p[2*ks+1][1]);
            pa[ks][3]=packh(p[2*ks+1][2],p[2*ks+1][3]);
        }

        // PV
#pragma unroll
        for(int ks=0;ks<4;ks++){
            uint32_t vb[4][4];
#pragma unroll
            for(int bt=0;bt<4;bt++){
                int row=bt*16+(lane&7)+((lane>>4)<<3);
                ldsm4(sb+vbuf+SWZ128((uint32_t)(row*128+(ks*16+((lane>>3)&1)*8)*2)),vb[bt]);
            }
#pragma unroll
            for(int nt=0;nt<8;nt++)
                mmah(o[nt],pa[ks],vb[nt>>1][(nt&1)*2],vb[nt>>1][(nt&1)*2+1]);
        }
    }

    const int b=bh>>4, h=bh&15;
    const float i0=1.f/l0_, i1=1.f/l1_;
    const int sr0=s0+16*w+q_, sr1=sr0+8;
#pragma unroll
    for(int nt=0;nt<8;nt++){
        int col=h*HDIM+nt*8+e0;
        *(float2*)&g_att[((size_t)(b*S_LEN+sr0))*D_MODEL+col]=make_float2(o[nt][0]*i0,o[nt][1]*i0);
        *(float2*)&g_att[((size_t)(b*S_LEN+sr1))*D_MODEL+col]=make_float2(o[nt][2]*i1,o[nt][3]*i1);
    }
}

// ------------------- LayerNorm -------------------
__global__ __launch_bounds__(256) void ln_kernel(
    const float* __restrict__ lw, const float* __restrict__ lb, float* __restrict__ out)
{
    __shared__ float red[16];
    const int row=blockIdx.x, tid=threadIdx.x;
    const float* xr=g_att+(size_t)row*D_MODEL;
    float4 v=*(const float4*)&xr[tid*4];
    float sum=v.x+v.y+v.z+v.w;
    float ss=fmaf(v.x,v.x,fmaf(v.y,v.y,fmaf(v.z,v.z,v.w*v.w)));
#pragma unroll
    for(int off=16;off;off>>=1){
        sum+=__shfl_xor_sync(~0u,sum,off);
        ss +=__shfl_xor_sync(~0u,ss,off);
    }
    if((tid&31)==0){ red[tid>>5]=sum; red[8+(tid>>5)]=ss; }
    __syncthreads();
    float ts=0.f,tq=0.f;
#pragma unroll
    for(int k=0;k<8;k++){ ts+=red[k]; tq+=red[8+k]; }
    float mu=ts*(1.f/D_MODEL), var=tq*(1.f/D_MODEL)-mu*mu;
    float rs=rsqrtf(var+1e-5f);
    float4 w4=*(const float4*)&lw[tid*4];
    float4 b4=*(const float4*)&lb[tid*4];
    float4 oo;
    oo.x=(v.x-mu)*rs*w4.x+b4.x; oo.y=(v.y-mu)*rs*w4.y+b4.y;
    oo.z=(v.z-mu)*rs*w4.z+b4.z; oo.w=(v.w-mu)*rs*w4.w+b4.w;
    *(float4*)&out[(size_t)row*D_MODEL+tid*4]=oo;
}

extern "C" void kernel_launch(void* const* d_in, const int* in_sizes, int n_in,
                              void* d_out, int out_size)
{
    (void)in_sizes; (void)n_in; (void)out_size;
    const float* x =(const float*)d_in[0];
    const float* Wq=(const float*)d_in[1];
    const float* Wk=(const float*)d_in[2];
    const float* Wv=(const float*)d_in[3];
    const float* Er=(const float*)d_in[4];
    const float* lw=(const float*)d_in[5];
    const float* lb=(const float*)d_in[6];
    float* out=(float*)d_out;

    convert_kernel<<<(CV_QUADS+255)/256,256>>>(x,Wq,Wk,Wv,Er);
    cudaFuncSetAttribute(qkv_mma_kernel, cudaFuncAttributeMaxDynamicSharedMemorySize, GEMM_SMEM);
    qkv_mma_kernel<<<dim3(8,32,3),256,GEMM_SMEM>>>();
    cudaFuncSetAttribute(attn_mma_kernel, cudaFuncAttributeMaxDynamicSharedMemorySize, ATT_SMEM);
    attn_mma_kernel<<<dim3(S_LEN/128,BHT),256,ATT_SMEM>>>();
    ln_kernel<<<NB*S_LEN,256>>>(lw,lb,out);
}